// round 2
// baseline (speedup 1.0000x reference)
#include <cuda_runtime.h>

#define NN 100000
#define NE 1600000

// ---- scratch (no allocations allowed; __device__ globals) ----
__device__ __align__(16) float g_dinv[NN];
__device__ __align__(16) float g_h1s[NN * 64];   // dinv-scaled layer-1 features (scatter source)
__device__ __align__(16) float g_agg1[NN * 64];  // accumulator (init = self-loop contribution)
__device__ __align__(16) float g_h2s[NN * 32];
__device__ __align__(16) float g_agg2[NN * 32];
__device__ __align__(16) float g_h3s[NN * 16];

__device__ __forceinline__ void red_add_v4(float* p, float4 v) {
    asm volatile("red.global.add.v4.f32 [%0], {%1,%2,%3,%4};"
                 :: "l"(p), "f"(v.x), "f"(v.y), "f"(v.z), "f"(v.w) : "memory");
}

// ---- degree / dinv ----
__global__ void k_deg_init() {
    int i = blockIdx.x * blockDim.x + threadIdx.x;
    if (i < NN) g_dinv[i] = 1.0f;   // self-loop
}
__global__ void k_deg_acc(const int* __restrict__ dst) {
    int e = blockIdx.x * blockDim.x + threadIdx.x;
    if (e < NE) atomicAdd(&g_dinv[dst[e]], 1.0f);  // exact integer sums in fp32
}
__global__ void k_deg_fin() {
    int i = blockIdx.x * blockDim.x + threadIdx.x;
    if (i < NN) g_dinv[i] = rsqrtf(g_dinv[i]);
}

// ---- GEMM1: h1s = dinv ⊙ (X @ W1), also writes agg1 init ----
// 128x64 tile per block, 128 threads, 8x8 microtile, K-tiles of 32.
__global__ void __launch_bounds__(128) k_gemm1(const float* __restrict__ X,
                                               const float* __restrict__ W) {
    __shared__ float As[32][140];   // transposed [k][row], pad 140 (16B aligned rows, 4-way max store conflict)
    __shared__ float Bs[32][64];    // [k][col]
    const int tid = threadIdx.x;
    const int row0 = blockIdx.x * 128;
    const int rt = tid >> 3;   // 0..15
    const int ct = tid & 7;    // 0..7
    float acc[8][8];
#pragma unroll
    for (int i = 0; i < 8; i++)
#pragma unroll
        for (int j = 0; j < 8; j++) acc[i][j] = 0.0f;

    for (int k0 = 0; k0 < 512; k0 += 32) {
        // A tile: 128 rows x 32 k = 1024 float4 items; coalesced (8 threads per row)
#pragma unroll
        for (int it = 0; it < 8; it++) {
            int i = it * 128 + tid;
            int r = i >> 3;
            int c4 = i & 7;
            int gr = row0 + r; if (gr >= NN) gr = NN - 1;
            float4 v = *(const float4*)(X + (size_t)gr * 512 + k0 + c4 * 4);
            As[c4 * 4 + 0][r] = v.x;
            As[c4 * 4 + 1][r] = v.y;
            As[c4 * 4 + 2][r] = v.z;
            As[c4 * 4 + 3][r] = v.w;
        }
        // B tile: 32 x 64 = 512 float4 items
#pragma unroll
        for (int it = 0; it < 4; it++) {
            int i = it * 128 + tid;
            int kk = i >> 4;
            int c4 = i & 15;
            *(float4*)(&Bs[kk][c4 * 4]) = *(const float4*)(W + (size_t)(k0 + kk) * 64 + c4 * 4);
        }
        __syncthreads();
#pragma unroll
        for (int k = 0; k < 32; k++) {
            float a[8], b[8];
            *(float4*)(a)     = *(float4*)(&As[k][rt * 8]);
            *(float4*)(a + 4) = *(float4*)(&As[k][rt * 8 + 4]);
            *(float4*)(b)     = *(float4*)(&Bs[k][ct * 8]);
            *(float4*)(b + 4) = *(float4*)(&Bs[k][ct * 8 + 4]);
#pragma unroll
            for (int i = 0; i < 8; i++)
#pragma unroll
                for (int j = 0; j < 8; j++) acc[i][j] = fmaf(a[i], b[j], acc[i][j]);
        }
        __syncthreads();
    }
#pragma unroll
    for (int i = 0; i < 8; i++) {
        int r = row0 + rt * 8 + i;
        if (r < NN) {
            float dv = g_dinv[r];
            float4 o0 = make_float4(acc[i][0] * dv, acc[i][1] * dv, acc[i][2] * dv, acc[i][3] * dv);
            float4 o1 = make_float4(acc[i][4] * dv, acc[i][5] * dv, acc[i][6] * dv, acc[i][7] * dv);
            float* p = g_h1s + (size_t)r * 64 + ct * 8;
            float* q = g_agg1 + (size_t)r * 64 + ct * 8;
            *(float4*)(p) = o0; *(float4*)(p + 4) = o1;
            *(float4*)(q) = o0; *(float4*)(q + 4) = o1;   // self-loop init
        }
    }
}

// ---- generic scatter: agg[dst] += h[src], float4 reductions ----
template <int L>
__global__ void k_scatter(const int* __restrict__ src, const int* __restrict__ dst,
                          float* __restrict__ outv) {
    constexpr int D4 = (L == 1) ? 16 : (L == 2) ? 8 : 4;
    const float* h = (L == 1) ? g_h1s : (L == 2) ? g_h2s : g_h3s;
    float* agg = (L == 1) ? g_agg1 : (L == 2) ? g_agg2 : outv;
    unsigned t = blockIdx.x * blockDim.x + threadIdx.x;
    unsigned e = t / D4;
    unsigned c = t % D4;
    if (e >= NE) return;
    int s = __ldg(src + e);
    int d = __ldg(dst + e);
    float4 v = *(const float4*)(h + (size_t)s * (4 * D4) + c * 4);
    red_add_v4(agg + (size_t)d * (4 * D4) + c * 4, v);
}

// ---- GEMM2: h2s = dinv ⊙ (relu(dinv ⊙ agg1 + b1) @ W2), writes agg2 init ----
__global__ void __launch_bounds__(256) k_gemm2(const float* __restrict__ W2,
                                               const float* __restrict__ b1) {
    __shared__ float Ts[64][68];     // transformed input tile, padded (conflict-free)
    __shared__ float Ws[64 * 32];
    const int tid = threadIdx.x;
    const int row0 = blockIdx.x * 64;
#pragma unroll
    for (int it = 0; it < 2; it++) {
        int i = it * 256 + tid;
        *(float4*)(Ws + i * 4) = *(const float4*)(W2 + i * 4);
    }
#pragma unroll
    for (int it = 0; it < 4; it++) {
        int i = it * 256 + tid;
        int r = i >> 4;
        int c4 = i & 15;
        int gr = row0 + r; if (gr >= NN) gr = NN - 1;
        float dv = g_dinv[gr];
        float4 v  = *(const float4*)(g_agg1 + (size_t)gr * 64 + c4 * 4);
        float4 bb = *(const float4*)(b1 + c4 * 4);
        v.x = fmaxf(fmaf(v.x, dv, bb.x), 0.0f);
        v.y = fmaxf(fmaf(v.y, dv, bb.y), 0.0f);
        v.z = fmaxf(fmaf(v.z, dv, bb.z), 0.0f);
        v.w = fmaxf(fmaf(v.w, dv, bb.w), 0.0f);
        *(float4*)(&Ts[r][c4 * 4]) = v;
    }
    __syncthreads();
    const int r = tid >> 2;    // 0..63
    const int cg = tid & 3;    // cols cg*8..cg*8+7
    float acc[8];
#pragma unroll
    for (int j = 0; j < 8; j++) acc[j] = 0.0f;
#pragma unroll
    for (int k = 0; k < 64; k++) {
        float a = Ts[r][k];
        float4 w0 = *(const float4*)(Ws + k * 32 + cg * 8);
        float4 w1 = *(const float4*)(Ws + k * 32 + cg * 8 + 4);
        acc[0] = fmaf(a, w0.x, acc[0]); acc[1] = fmaf(a, w0.y, acc[1]);
        acc[2] = fmaf(a, w0.z, acc[2]); acc[3] = fmaf(a, w0.w, acc[3]);
        acc[4] = fmaf(a, w1.x, acc[4]); acc[5] = fmaf(a, w1.y, acc[5]);
        acc[6] = fmaf(a, w1.z, acc[6]); acc[7] = fmaf(a, w1.w, acc[7]);
    }
    int gr = row0 + r;
    if (gr < NN) {
        float dv = g_dinv[gr];
        float4 o0 = make_float4(acc[0] * dv, acc[1] * dv, acc[2] * dv, acc[3] * dv);
        float4 o1 = make_float4(acc[4] * dv, acc[5] * dv, acc[6] * dv, acc[7] * dv);
        float* p = g_h2s + (size_t)gr * 32 + cg * 8;
        float* q = g_agg2 + (size_t)gr * 32 + cg * 8;
        *(float4*)(p) = o0; *(float4*)(p + 4) = o1;
        *(float4*)(q) = o0; *(float4*)(q + 4) = o1;
    }
}

// ---- GEMM3: h3s = dinv ⊙ (relu(dinv ⊙ agg2 + b2) @ W3), writes d_out init ----
__global__ void __launch_bounds__(256) k_gemm3(const float* __restrict__ W3,
                                               const float* __restrict__ b2,
                                               float* __restrict__ outv) {
    __shared__ float Ts[64][36];
    __shared__ float Ws[32 * 16];
    const int tid = threadIdx.x;
    const int row0 = blockIdx.x * 64;
    if (tid < 128) *(float4*)(Ws + tid * 4) = *(const float4*)(W3 + tid * 4);
#pragma unroll
    for (int it = 0; it < 2; it++) {
        int i = it * 256 + tid;
        int r = i >> 3;
        int c4 = i & 7;
        int gr = row0 + r; if (gr >= NN) gr = NN - 1;
        float dv = g_dinv[gr];
        float4 v  = *(const float4*)(g_agg2 + (size_t)gr * 32 + c4 * 4);
        float4 bb = *(const float4*)(b2 + c4 * 4);
        v.x = fmaxf(fmaf(v.x, dv, bb.x), 0.0f);
        v.y = fmaxf(fmaf(v.y, dv, bb.y), 0.0f);
        v.z = fmaxf(fmaf(v.z, dv, bb.z), 0.0f);
        v.w = fmaxf(fmaf(v.w, dv, bb.w), 0.0f);
        *(float4*)(&Ts[r][c4 * 4]) = v;
    }
    __syncthreads();
    const int r = tid >> 2;   // 0..63
    const int cg = tid & 3;   // cols cg*4..cg*4+3
    float acc[4] = {0.0f, 0.0f, 0.0f, 0.0f};
#pragma unroll
    for (int k = 0; k < 32; k++) {
        float a = Ts[r][k];
        float4 w = *(const float4*)(Ws + k * 16 + cg * 4);
        acc[0] = fmaf(a, w.x, acc[0]); acc[1] = fmaf(a, w.y, acc[1]);
        acc[2] = fmaf(a, w.z, acc[2]); acc[3] = fmaf(a, w.w, acc[3]);
    }
    int gr = row0 + r;
    if (gr < NN) {
        float dv = g_dinv[gr];
        float4 o = make_float4(acc[0] * dv, acc[1] * dv, acc[2] * dv, acc[3] * dv);
        *(float4*)(g_h3s + (size_t)gr * 16 + cg * 4) = o;
        *(float4*)(outv + (size_t)gr * 16 + cg * 4) = o;   // self-loop init in d_out
    }
}

// ---- final: v = dinv*agg3 + b3; log_softmax in place ----
__global__ void k_final(const float* __restrict__ b3, float* __restrict__ outv) {
    int r = blockIdx.x * blockDim.x + threadIdx.x;
    if (r >= NN) return;
    float dv = g_dinv[r];
    float v[16];
    float4* p = (float4*)(outv + (size_t)r * 16);
#pragma unroll
    for (int i = 0; i < 4; i++) {
        float4 a = p[i];
        float4 bb = *(const float4*)(b3 + i * 4);
        v[i * 4 + 0] = fmaf(a.x, dv, bb.x);
        v[i * 4 + 1] = fmaf(a.y, dv, bb.y);
        v[i * 4 + 2] = fmaf(a.z, dv, bb.z);
        v[i * 4 + 3] = fmaf(a.w, dv, bb.w);
    }
    float m = v[0];
#pragma unroll
    for (int c = 1; c < 16; c++) m = fmaxf(m, v[c]);
    float s = 0.0f;
#pragma unroll
    for (int c = 0; c < 16; c++) s += expf(v[c] - m);
    float lse = m + logf(s);
#pragma unroll
    for (int i = 0; i < 4; i++) {
        float4 o = make_float4(v[i * 4 + 0] - lse, v[i * 4 + 1] - lse,
                               v[i * 4 + 2] - lse, v[i * 4 + 3] - lse);
        p[i] = o;
    }
}

extern "C" void kernel_launch(void* const* d_in, const int* in_sizes, int n_in,
                              void* d_out, int out_size) {
    const float* x  = (const float*)d_in[0];
    const int*   ei = (const int*)d_in[1];
    const float* W1 = (const float*)d_in[2];
    const float* b1 = (const float*)d_in[3];
    const float* W2 = (const float*)d_in[4];
    const float* b2 = (const float*)d_in[5];
    const float* W3 = (const float*)d_in[6];
    const float* b3 = (const float*)d_in[7];
    float* out = (float*)d_out;
    const int* src = ei;          // edge_index[0]
    const int* dst = ei + NE;     // edge_index[1]

    k_deg_init<<<(NN + 255) / 256, 256>>>();
    k_deg_acc<<<(NE + 255) / 256, 256>>>(dst);
    k_deg_fin<<<(NN + 255) / 256, 256>>>();

    k_gemm1<<<(NN + 127) / 128, 128>>>(x, W1);
    {
        unsigned total = (unsigned)NE * 16;
        k_scatter<1><<<(total + 255) / 256, 256>>>(src, dst, out);
    }
    k_gemm2<<<(NN + 63) / 64, 256>>>(W2, b1);
    {
        unsigned total = (unsigned)NE * 8;
        k_scatter<2><<<(total + 255) / 256, 256>>>(src, dst, out);
    }
    k_gemm3<<<(NN + 63) / 64, 256>>>(W3, b2, out);
    {
        unsigned total = (unsigned)NE * 4;
        k_scatter<3><<<(total + 255) / 256, 256>>>(src, dst, out);
    }
    k_final<<<(NN + 255) / 256, 256>>>(b3, out);
}

// round 3
// speedup vs baseline: 1.3461x; 1.3461x over previous
#include <cuda_runtime.h>

#define NN 100000
#define NE 1600000

// ---- scratch (no allocations allowed; __device__ globals) ----
__device__ __align__(16) float g_dinv[NN];
__device__ __align__(16) float g_h1s[NN * 64];   // dinv-scaled layer-1 features (scatter source)
__device__ __align__(16) float g_agg1[NN * 64];  // accumulator (init = self-loop contribution)
__device__ __align__(16) float g_h2s[NN * 32];
__device__ __align__(16) float g_agg2[NN * 32];
__device__ __align__(16) float g_h3s[NN * 16];

__device__ __forceinline__ void red_add_v4(float* p, float4 v) {
    asm volatile("red.global.add.v4.f32 [%0], {%1,%2,%3,%4};"
                 :: "l"(p), "f"(v.x), "f"(v.y), "f"(v.z), "f"(v.w) : "memory");
}

__device__ __forceinline__ unsigned f2tf(float f) {
    unsigned u;
    asm("cvt.rna.tf32.f32 %0, %1;" : "=r"(u) : "f"(f));
    return u;
}

// ---- degree / dinv ----
__global__ void k_deg_init() {
    int i = blockIdx.x * blockDim.x + threadIdx.x;
    if (i < NN) g_dinv[i] = 1.0f;   // self-loop
}
__global__ void k_deg_acc(const int* __restrict__ dst) {
    int e = blockIdx.x * blockDim.x + threadIdx.x;
    if (e < NE) atomicAdd(&g_dinv[dst[e]], 1.0f);  // exact integer sums in fp32
}
__global__ void k_deg_fin() {
    int i = blockIdx.x * blockDim.x + threadIdx.x;
    if (i < NN) g_dinv[i] = rsqrtf(g_dinv[i]);
}

// ---- GEMM1 (TF32 tensor cores): h1s = dinv ⊙ (X @ W1), also writes agg1 init ----
// Block tile 128x64, 128 threads (4 warps), warp tile 32x64 via m16n8k8 tf32 mma.
// Double-buffered smem, BK=16, explicit cvt.rna.tf32.f32 during staging.
__global__ void __launch_bounds__(128) k_gemm1(const float* __restrict__ X,
                                               const float* __restrict__ W) {
    __shared__ unsigned As[2][128 * 20];  // [row][k], pad 20 (frag LDS conflict-free)
    __shared__ unsigned Bs[2][16 * 72];   // [k][n],   pad 72 (stride mod 32 == 8)
    const int tid = threadIdx.x;
    const int lane = tid & 31;
    const int w = tid >> 5;
    const int row0 = blockIdx.x * 128;
    const int g = lane >> 2;      // group id 0..7
    const int tg = lane & 3;      // thread-in-group 0..3

    float c[2][8][4];
#pragma unroll
    for (int mt = 0; mt < 2; mt++)
#pragma unroll
        for (int nt = 0; nt < 8; nt++)
#pragma unroll
            for (int q = 0; q < 4; q++) c[mt][nt][q] = 0.0f;

    float4 ra[4], rb[2];

#define LDA(kt)                                                                 \
    {                                                                           \
        _Pragma("unroll") for (int it = 0; it < 4; it++) {                      \
            int i = it * 128 + tid;                                             \
            int r = i >> 2, kq = i & 3;                                         \
            int gr = row0 + r; if (gr >= NN) gr = NN - 1;                       \
            ra[it] = *(const float4*)(X + (size_t)gr * 512 + (kt) * 16 + kq * 4); \
        }                                                                       \
    }
#define LDB(kt)                                                                 \
    {                                                                           \
        _Pragma("unroll") for (int it = 0; it < 2; it++) {                      \
            int i = it * 128 + tid;                                             \
            int k = i >> 4, n4 = i & 15;                                        \
            rb[it] = *(const float4*)(W + (size_t)((kt) * 16 + k) * 64 + n4 * 4); \
        }                                                                       \
    }
#define STAB(buf)                                                               \
    {                                                                           \
        _Pragma("unroll") for (int it = 0; it < 4; it++) {                      \
            int i = it * 128 + tid;                                             \
            int r = i >> 2, kq = i & 3;                                         \
            uint4 u = make_uint4(f2tf(ra[it].x), f2tf(ra[it].y),                \
                                 f2tf(ra[it].z), f2tf(ra[it].w));               \
            *(uint4*)(&As[buf][r * 20 + kq * 4]) = u;                           \
        }                                                                       \
        _Pragma("unroll") for (int it = 0; it < 2; it++) {                      \
            int i = it * 128 + tid;                                             \
            int k = i >> 4, n4 = i & 15;                                        \
            uint4 u = make_uint4(f2tf(rb[it].x), f2tf(rb[it].y),                \
                                 f2tf(rb[it].z), f2tf(rb[it].w));               \
            *(uint4*)(&Bs[buf][k * 72 + n4 * 4]) = u;                           \
        }                                                                       \
    }

    LDA(0); LDB(0);
    STAB(0);
    __syncthreads();

    for (int kt = 0; kt < 32; kt++) {
        int buf = kt & 1;
        if (kt < 31) { LDA(kt + 1); LDB(kt + 1); }
        // compute on buf
#pragma unroll
        for (int kk = 0; kk < 16; kk += 8) {
            unsigned a[2][4];
#pragma unroll
            for (int mt = 0; mt < 2; mt++) {
                int r = w * 32 + mt * 16 + g;
                a[mt][0] = As[buf][r * 20 + kk + tg];
                a[mt][1] = As[buf][(r + 8) * 20 + kk + tg];
                a[mt][2] = As[buf][r * 20 + kk + tg + 4];
                a[mt][3] = As[buf][(r + 8) * 20 + kk + tg + 4];
            }
            unsigned b[8][2];
#pragma unroll
            for (int nt = 0; nt < 8; nt++) {
                int n = nt * 8 + g;
                b[nt][0] = Bs[buf][(kk + tg) * 72 + n];
                b[nt][1] = Bs[buf][(kk + tg + 4) * 72 + n];
            }
#pragma unroll
            for (int mt = 0; mt < 2; mt++)
#pragma unroll
                for (int nt = 0; nt < 8; nt++)
                    asm volatile(
                        "mma.sync.aligned.m16n8k8.row.col.f32.tf32.tf32.f32 "
                        "{%0,%1,%2,%3}, {%4,%5,%6,%7}, {%8,%9}, {%0,%1,%2,%3};"
                        : "+f"(c[mt][nt][0]), "+f"(c[mt][nt][1]),
                          "+f"(c[mt][nt][2]), "+f"(c[mt][nt][3])
                        : "r"(a[mt][0]), "r"(a[mt][1]), "r"(a[mt][2]), "r"(a[mt][3]),
                          "r"(b[nt][0]), "r"(b[nt][1]));
        }
        if (kt < 31) {
            __syncthreads();
            STAB(buf ^ 1);
            __syncthreads();
        }
    }
#undef LDA
#undef LDB
#undef STAB

    // epilogue: scale by dinv, write h1s and agg1 (self-loop init)
#pragma unroll
    for (int mt = 0; mt < 2; mt++) {
        int r_base = row0 + w * 32 + mt * 16 + g;
#pragma unroll
        for (int half = 0; half < 2; half++) {
            int r = r_base + half * 8;
            if (r < NN) {
                float dv = g_dinv[r];
#pragma unroll
                for (int nt = 0; nt < 8; nt++) {
                    float2 o;
                    o.x = c[mt][nt][half * 2 + 0] * dv;
                    o.y = c[mt][nt][half * 2 + 1] * dv;
                    int col = nt * 8 + 2 * tg;
                    *(float2*)(g_h1s + (size_t)r * 64 + col) = o;
                    *(float2*)(g_agg1 + (size_t)r * 64 + col) = o;
                }
            }
        }
    }
}

// ---- generic scatter: agg[dst] += h[src], float4 reductions ----
template <int L>
__global__ void k_scatter(const int* __restrict__ src, const int* __restrict__ dst,
                          float* __restrict__ outv) {
    constexpr int D4 = (L == 1) ? 16 : (L == 2) ? 8 : 4;
    const float* h = (L == 1) ? g_h1s : (L == 2) ? g_h2s : g_h3s;
    float* agg = (L == 1) ? g_agg1 : (L == 2) ? g_agg2 : outv;
    unsigned t = blockIdx.x * blockDim.x + threadIdx.x;
    unsigned e = t / D4;
    unsigned c = t % D4;
    if (e >= NE) return;
    int s = __ldg(src + e);
    int d = __ldg(dst + e);
    float4 v = *(const float4*)(h + (size_t)s * (4 * D4) + c * 4);
    red_add_v4(agg + (size_t)d * (4 * D4) + c * 4, v);
}

// ---- GEMM2: h2s = dinv ⊙ (relu(dinv ⊙ agg1 + b1) @ W2), writes agg2 init ----
__global__ void __launch_bounds__(256) k_gemm2(const float* __restrict__ W2,
                                               const float* __restrict__ b1) {
    __shared__ float Ts[64][68];
    __shared__ float Ws[64 * 32];
    const int tid = threadIdx.x;
    const int row0 = blockIdx.x * 64;
#pragma unroll
    for (int it = 0; it < 2; it++) {
        int i = it * 256 + tid;
        *(float4*)(Ws + i * 4) = *(const float4*)(W2 + i * 4);
    }
#pragma unroll
    for (int it = 0; it < 4; it++) {
        int i = it * 256 + tid;
        int r = i >> 4;
        int c4 = i & 15;
        int gr = row0 + r; if (gr >= NN) gr = NN - 1;
        float dv = g_dinv[gr];
        float4 v  = *(const float4*)(g_agg1 + (size_t)gr * 64 + c4 * 4);
        float4 bb = *(const float4*)(b1 + c4 * 4);
        v.x = fmaxf(fmaf(v.x, dv, bb.x), 0.0f);
        v.y = fmaxf(fmaf(v.y, dv, bb.y), 0.0f);
        v.z = fmaxf(fmaf(v.z, dv, bb.z), 0.0f);
        v.w = fmaxf(fmaf(v.w, dv, bb.w), 0.0f);
        *(float4*)(&Ts[r][c4 * 4]) = v;
    }
    __syncthreads();
    const int r = tid >> 2;
    const int cg = tid & 3;
    float acc[8];
#pragma unroll
    for (int j = 0; j < 8; j++) acc[j] = 0.0f;
#pragma unroll
    for (int k = 0; k < 64; k++) {
        float a = Ts[r][k];
        float4 w0 = *(const float4*)(Ws + k * 32 + cg * 8);
        float4 w1 = *(const float4*)(Ws + k * 32 + cg * 8 + 4);
        acc[0] = fmaf(a, w0.x, acc[0]); acc[1] = fmaf(a, w0.y, acc[1]);
        acc[2] = fmaf(a, w0.z, acc[2]); acc[3] = fmaf(a, w0.w, acc[3]);
        acc[4] = fmaf(a, w1.x, acc[4]); acc[5] = fmaf(a, w1.y, acc[5]);
        acc[6] = fmaf(a, w1.z, acc[6]); acc[7] = fmaf(a, w1.w, acc[7]);
    }
    int gr = row0 + r;
    if (gr < NN) {
        float dv = g_dinv[gr];
        float4 o0 = make_float4(acc[0] * dv, acc[1] * dv, acc[2] * dv, acc[3] * dv);
        float4 o1 = make_float4(acc[4] * dv, acc[5] * dv, acc[6] * dv, acc[7] * dv);
        float* p = g_h2s + (size_t)gr * 32 + cg * 8;
        float* q = g_agg2 + (size_t)gr * 32 + cg * 8;
        *(float4*)(p) = o0; *(float4*)(p + 4) = o1;
        *(float4*)(q) = o0; *(float4*)(q + 4) = o1;
    }
}

// ---- GEMM3: h3s = dinv ⊙ (relu(dinv ⊙ agg2 + b2) @ W3), writes d_out init ----
__global__ void __launch_bounds__(256) k_gemm3(const float* __restrict__ W3,
                                               const float* __restrict__ b2,
                                               float* __restrict__ outv) {
    __shared__ float Ts[64][36];
    __shared__ float Ws[32 * 16];
    const int tid = threadIdx.x;
    const int row0 = blockIdx.x * 64;
    if (tid < 128) *(float4*)(Ws + tid * 4) = *(const float4*)(W3 + tid * 4);
#pragma unroll
    for (int it = 0; it < 2; it++) {
        int i = it * 256 + tid;
        int r = i >> 3;
        int c4 = i & 7;
        int gr = row0 + r; if (gr >= NN) gr = NN - 1;
        float dv = g_dinv[gr];
        float4 v  = *(const float4*)(g_agg2 + (size_t)gr * 32 + c4 * 4);
        float4 bb = *(const float4*)(b2 + c4 * 4);
        v.x = fmaxf(fmaf(v.x, dv, bb.x), 0.0f);
        v.y = fmaxf(fmaf(v.y, dv, bb.y), 0.0f);
        v.z = fmaxf(fmaf(v.z, dv, bb.z), 0.0f);
        v.w = fmaxf(fmaf(v.w, dv, bb.w), 0.0f);
        *(float4*)(&Ts[r][c4 * 4]) = v;
    }
    __syncthreads();
    const int r = tid >> 2;
    const int cg = tid & 3;
    float acc[4] = {0.0f, 0.0f, 0.0f, 0.0f};
#pragma unroll
    for (int k = 0; k < 32; k++) {
        float a = Ts[r][k];
        float4 w = *(const float4*)(Ws + k * 16 + cg * 4);
        acc[0] = fmaf(a, w.x, acc[0]); acc[1] = fmaf(a, w.y, acc[1]);
        acc[2] = fmaf(a, w.z, acc[2]); acc[3] = fmaf(a, w.w, acc[3]);
    }
    int gr = row0 + r;
    if (gr < NN) {
        float dv = g_dinv[gr];
        float4 o = make_float4(acc[0] * dv, acc[1] * dv, acc[2] * dv, acc[3] * dv);
        *(float4*)(g_h3s + (size_t)gr * 16 + cg * 4) = o;
        *(float4*)(outv + (size_t)gr * 16 + cg * 4) = o;   // self-loop init in d_out
    }
}

// ---- final: v = dinv*agg3 + b3; log_softmax in place ----
__global__ void k_final(const float* __restrict__ b3, float* __restrict__ outv) {
    int r = blockIdx.x * blockDim.x + threadIdx.x;
    if (r >= NN) return;
    float dv = g_dinv[r];
    float v[16];
    float4* p = (float4*)(outv + (size_t)r * 16);
#pragma unroll
    for (int i = 0; i < 4; i++) {
        float4 a = p[i];
        float4 bb = *(const float4*)(b3 + i * 4);
        v[i * 4 + 0] = fmaf(a.x, dv, bb.x);
        v[i * 4 + 1] = fmaf(a.y, dv, bb.y);
        v[i * 4 + 2] = fmaf(a.z, dv, bb.z);
        v[i * 4 + 3] = fmaf(a.w, dv, bb.w);
    }
    float m = v[0];
#pragma unroll
    for (int c = 1; c < 16; c++) m = fmaxf(m, v[c]);
    float s = 0.0f;
#pragma unroll
    for (int c = 0; c < 16; c++) s += expf(v[c] - m);
    float lse = m + logf(s);
#pragma unroll
    for (int i = 0; i < 4; i++) {
        float4 o = make_float4(v[i * 4 + 0] - lse, v[i * 4 + 1] - lse,
                               v[i * 4 + 2] - lse, v[i * 4 + 3] - lse);
        p[i] = o;
    }
}

extern "C" void kernel_launch(void* const* d_in, const int* in_sizes, int n_in,
                              void* d_out, int out_size) {
    const float* x  = (const float*)d_in[0];
    const int*   ei = (const int*)d_in[1];
    const float* W1 = (const float*)d_in[2];
    const float* b1 = (const float*)d_in[3];
    const float* W2 = (const float*)d_in[4];
    const float* b2 = (const float*)d_in[5];
    const float* W3 = (const float*)d_in[6];
    const float* b3 = (const float*)d_in[7];
    float* out = (float*)d_out;
    const int* src = ei;          // edge_index[0]
    const int* dst = ei + NE;     // edge_index[1]

    k_deg_init<<<(NN + 255) / 256, 256>>>();
    k_deg_acc<<<(NE + 255) / 256, 256>>>(dst);
    k_deg_fin<<<(NN + 255) / 256, 256>>>();

    k_gemm1<<<(NN + 127) / 128, 128>>>(x, W1);
    {
        unsigned total = (unsigned)NE * 16;
        k_scatter<1><<<(total + 255) / 256, 256>>>(src, dst, out);
    }
    k_gemm2<<<(NN + 63) / 64, 256>>>(W2, b1);
    {
        unsigned total = (unsigned)NE * 8;
        k_scatter<2><<<(total + 255) / 256, 256>>>(src, dst, out);
    }
    k_gemm3<<<(NN + 63) / 64, 256>>>(W3, b2, out);
    {
        unsigned total = (unsigned)NE * 4;
        k_scatter<3><<<(total + 255) / 256, 256>>>(src, dst, out);
    }
    k_final<<<(NN + 255) / 256, 256>>>(b3, out);
}

// round 4
// speedup vs baseline: 1.7831x; 1.3247x over previous
#include <cuda_runtime.h>

#define NN 100000
#define NE 1600000
#define NB_SCAN 98   // ceil(NN/1024)

// ---- scratch (__device__ globals; no allocations allowed) ----
__device__ __align__(16) float g_dinv[NN];
__device__ __align__(16) float g_h1s[NN * 64];   // dinv-scaled layer-1 features
__device__ __align__(16) float g_agg1[NN * 64];
__device__ __align__(16) float g_h2s[NN * 32];
__device__ __align__(16) float g_agg2[NN * 32];
__device__ __align__(16) float g_h3s[NN * 16];
__device__ int g_degi[NN];
__device__ int g_off[NN + 1];
__device__ int g_cur[NN];
__device__ int g_bsum[128];
__device__ int g_eidx[NE];

// ================= CSR build + dinv =================
__global__ void k_zero() {
    int i = blockIdx.x * blockDim.x + threadIdx.x;
    if (i < NN) g_degi[i] = 0;
}
__global__ void k_hist(const int* __restrict__ dst) {
    int e = blockIdx.x * blockDim.x + threadIdx.x;
    if (e < NE) atomicAdd(&g_degi[dst[e]], 1);
}
// per-block exclusive scan (1024 elems/block), block totals -> g_bsum
__global__ void __launch_bounds__(1024) k_scan1() {
    __shared__ int sm[1024];
    int tid = threadIdx.x;
    int i = blockIdx.x * 1024 + tid;
    int v = (i < NN) ? g_degi[i] : 0;
    sm[tid] = v;
    __syncthreads();
#pragma unroll
    for (int s = 1; s < 1024; s <<= 1) {
        int t = (tid >= s) ? sm[tid - s] : 0;
        __syncthreads();
        sm[tid] += t;
        __syncthreads();
    }
    if (i < NN) g_off[i] = sm[tid] - v;   // exclusive within block
    if (tid == 1023) g_bsum[blockIdx.x] = sm[1023];
}
// scan the 98 block totals (exclusive), single block
__global__ void __launch_bounds__(128) k_scan2() {
    __shared__ int sm[128];
    int tid = threadIdx.x;
    int v = (tid < NB_SCAN) ? g_bsum[tid] : 0;
    sm[tid] = v;
    __syncthreads();
#pragma unroll
    for (int s = 1; s < 128; s <<= 1) {
        int t = (tid >= s) ? sm[tid - s] : 0;
        __syncthreads();
        sm[tid] += t;
        __syncthreads();
    }
    if (tid < NB_SCAN) g_bsum[tid] = sm[tid] - v;
}
// add block prefixes, write cursor copy, dinv, sentinel
__global__ void __launch_bounds__(1024) k_scan3() {
    int i = blockIdx.x * 1024 + threadIdx.x;
    if (i < NN) {
        int o = g_off[i] + g_bsum[blockIdx.x];
        g_off[i] = o;
        g_cur[i] = o;
        g_dinv[i] = rsqrtf((float)(1 + g_degi[i]));   // +1 = self-loop
    }
    if (i == 0) g_off[NN] = NE;
}
__global__ void k_fill(const int* __restrict__ src, const int* __restrict__ dst) {
    int e = blockIdx.x * blockDim.x + threadIdx.x;
    if (e < NE) {
        int p = atomicAdd(&g_cur[dst[e]], 1);
        g_eidx[p] = src[e];
    }
}

// ================= GEMM1 (TF32 MMA, cp.async 3-stage) =================
// h1s = dinv ⊙ (X @ W1). Block 128x64, 128 threads, warp tile 32x64.
__global__ void __launch_bounds__(128) k_gemm1(const float* __restrict__ X,
                                               const float* __restrict__ W) {
    __shared__ unsigned As[3][128 * 20];  // [row][k] pad 20
    __shared__ unsigned Bs[3][16 * 72];   // [k][n]   pad 72
    const int tid = threadIdx.x;
    const int lane = tid & 31;
    const int w = tid >> 5;
    const int row0 = blockIdx.x * 128;
    const int g = lane >> 2;
    const int tg = lane & 3;

    float c[2][8][4];
#pragma unroll
    for (int mt = 0; mt < 2; mt++)
#pragma unroll
        for (int nt = 0; nt < 8; nt++)
#pragma unroll
            for (int q = 0; q < 4; q++) c[mt][nt][q] = 0.0f;

#define ISSUE(kt, st)                                                            \
    {                                                                            \
        _Pragma("unroll") for (int it = 0; it < 4; it++) {                       \
            int i = it * 128 + tid;                                              \
            int r = i >> 2, kq = i & 3;                                          \
            int gr = row0 + r; if (gr >= NN) gr = NN - 1;                        \
            const float* gp = X + (size_t)gr * 512 + (kt) * 16 + kq * 4;         \
            unsigned sa = (unsigned)__cvta_generic_to_shared(&As[st][r * 20 + kq * 4]); \
            asm volatile("cp.async.cg.shared.global [%0], [%1], 16;" ::          \
                         "r"(sa), "l"(gp));                                      \
        }                                                                        \
        _Pragma("unroll") for (int it = 0; it < 2; it++) {                       \
            int i = it * 128 + tid;                                              \
            int k = i >> 4, n4 = i & 15;                                         \
            const float* gp = W + (size_t)((kt) * 16 + k) * 64 + n4 * 4;         \
            unsigned sa = (unsigned)__cvta_generic_to_shared(&Bs[st][k * 72 + n4 * 4]); \
            asm volatile("cp.async.cg.shared.global [%0], [%1], 16;" ::          \
                         "r"(sa), "l"(gp));                                      \
        }                                                                        \
        asm volatile("cp.async.commit_group;");                                  \
    }

    ISSUE(0, 0);
    ISSUE(1, 1);

    for (int kt = 0; kt < 32; kt++) {
        const int st = kt % 3;
        asm volatile("cp.async.wait_group 1;");
        __syncthreads();
        if (kt + 2 < 32) {
            const int st2 = (kt + 2) % 3;
            ISSUE(kt + 2, st2);
        } else {
            asm volatile("cp.async.commit_group;");
        }
        // compute on stage st (raw fp32 bits consumed as tf32 — truncation)
#pragma unroll
        for (int kk = 0; kk < 16; kk += 8) {
            unsigned a[2][4];
#pragma unroll
            for (int mt = 0; mt < 2; mt++) {
                int r = w * 32 + mt * 16 + g;
                a[mt][0] = As[st][r * 20 + kk + tg];
                a[mt][1] = As[st][(r + 8) * 20 + kk + tg];
                a[mt][2] = As[st][r * 20 + kk + tg + 4];
                a[mt][3] = As[st][(r + 8) * 20 + kk + tg + 4];
            }
            unsigned b[8][2];
#pragma unroll
            for (int nt = 0; nt < 8; nt++) {
                int n = nt * 8 + g;
                b[nt][0] = Bs[st][(kk + tg) * 72 + n];
                b[nt][1] = Bs[st][(kk + tg + 4) * 72 + n];
            }
#pragma unroll
            for (int mt = 0; mt < 2; mt++)
#pragma unroll
                for (int nt = 0; nt < 8; nt++)
                    asm volatile(
                        "mma.sync.aligned.m16n8k8.row.col.f32.tf32.tf32.f32 "
                        "{%0,%1,%2,%3}, {%4,%5,%6,%7}, {%8,%9}, {%0,%1,%2,%3};"
                        : "+f"(c[mt][nt][0]), "+f"(c[mt][nt][1]),
                          "+f"(c[mt][nt][2]), "+f"(c[mt][nt][3])
                        : "r"(a[mt][0]), "r"(a[mt][1]), "r"(a[mt][2]), "r"(a[mt][3]),
                          "r"(b[nt][0]), "r"(b[nt][1]));
        }
    }
#undef ISSUE

    // epilogue: scale by dinv, write h1s only (gather initializes from h1s[n])
#pragma unroll
    for (int mt = 0; mt < 2; mt++) {
        int r_base = row0 + w * 32 + mt * 16 + g;
#pragma unroll
        for (int half = 0; half < 2; half++) {
            int r = r_base + half * 8;
            if (r < NN) {
                float dv = g_dinv[r];
#pragma unroll
                for (int nt = 0; nt < 8; nt++) {
                    float2 o;
                    o.x = c[mt][nt][half * 2 + 0] * dv;
                    o.y = c[mt][nt][half * 2 + 1] * dv;
                    *(float2*)(g_h1s + (size_t)r * 64 + nt * 8 + 2 * tg) = o;
                }
            }
        }
    }
}

// ================= CSR gathers (no atomics) =================
// Layer 1: 64 feats, warp per node, 2 accs/lane.
__global__ void __launch_bounds__(256) k_gather64() {
    int n = (blockIdx.x * 256 + threadIdx.x) >> 5;
    int lane = threadIdx.x & 31;
    if (n >= NN) return;
    int j = g_off[n], e = g_off[n + 1];
    float a0 = g_h1s[(size_t)n * 64 + lane];          // self-loop
    float a1 = g_h1s[(size_t)n * 64 + 32 + lane];
    for (; j + 1 < e; j += 2) {
        int s0 = __ldg(&g_eidx[j]);
        int s1 = __ldg(&g_eidx[j + 1]);
        a0 += __ldg(&g_h1s[(size_t)s0 * 64 + lane]);
        a1 += __ldg(&g_h1s[(size_t)s0 * 64 + 32 + lane]);
        a0 += __ldg(&g_h1s[(size_t)s1 * 64 + lane]);
        a1 += __ldg(&g_h1s[(size_t)s1 * 64 + 32 + lane]);
    }
    if (j < e) {
        int s0 = __ldg(&g_eidx[j]);
        a0 += __ldg(&g_h1s[(size_t)s0 * 64 + lane]);
        a1 += __ldg(&g_h1s[(size_t)s0 * 64 + 32 + lane]);
    }
    g_agg1[(size_t)n * 64 + lane] = a0;
    g_agg1[(size_t)n * 64 + 32 + lane] = a1;
}
// Layer 2: 32 feats, warp per node.
__global__ void __launch_bounds__(256) k_gather32() {
    int n = (blockIdx.x * 256 + threadIdx.x) >> 5;
    int lane = threadIdx.x & 31;
    if (n >= NN) return;
    int j = g_off[n], e = g_off[n + 1];
    float a0 = g_h2s[(size_t)n * 32 + lane];
    for (; j + 1 < e; j += 2) {
        int s0 = __ldg(&g_eidx[j]);
        int s1 = __ldg(&g_eidx[j + 1]);
        a0 += __ldg(&g_h2s[(size_t)s0 * 32 + lane]);
        a0 += __ldg(&g_h2s[(size_t)s1 * 32 + lane]);
    }
    if (j < e) a0 += __ldg(&g_h2s[(size_t)__ldg(&g_eidx[j]) * 32 + lane]);
    g_agg2[(size_t)n * 32 + lane] = a0;
}
// Layer 3 + bias + log_softmax fused: 16-lane group per node.
__global__ void __launch_bounds__(256) k_gather16_final(const float* __restrict__ b3,
                                                        float* __restrict__ outv) {
    int t = blockIdx.x * 256 + threadIdx.x;
    int n = t >> 4;
    int f = t & 15;
    if (n >= NN) return;
    int j = g_off[n], e = g_off[n + 1];
    float a = g_h3s[(size_t)n * 16 + f];
    for (; j + 1 < e; j += 2) {
        int s0 = __ldg(&g_eidx[j]);
        int s1 = __ldg(&g_eidx[j + 1]);
        a += __ldg(&g_h3s[(size_t)s0 * 16 + f]);
        a += __ldg(&g_h3s[(size_t)s1 * 16 + f]);
    }
    if (j < e) a += __ldg(&g_h3s[(size_t)__ldg(&g_eidx[j]) * 16 + f]);
    float v = fmaf(a, g_dinv[n], __ldg(&b3[f]));
    float m = v;
#pragma unroll
    for (int s = 8; s >= 1; s >>= 1) m = fmaxf(m, __shfl_xor_sync(0xffffffffu, m, s));
    float su = expf(v - m);
#pragma unroll
    for (int s = 8; s >= 1; s >>= 1) su += __shfl_xor_sync(0xffffffffu, su, s);
    float lse = m + logf(su);
    outv[(size_t)n * 16 + f] = v - lse;
}

// ================= small GEMMs (fused relu/bias/scale) =================
__global__ void __launch_bounds__(256) k_gemm2(const float* __restrict__ W2,
                                               const float* __restrict__ b1) {
    __shared__ float Ts[64][68];
    __shared__ float Ws[64 * 32];
    const int tid = threadIdx.x;
    const int row0 = blockIdx.x * 64;
#pragma unroll
    for (int it = 0; it < 2; it++) {
        int i = it * 256 + tid;
        *(float4*)(Ws + i * 4) = *(const float4*)(W2 + i * 4);
    }
#pragma unroll
    for (int it = 0; it < 4; it++) {
        int i = it * 256 + tid;
        int r = i >> 4;
        int c4 = i & 15;
        int gr = row0 + r; if (gr >= NN) gr = NN - 1;
        float dv = g_dinv[gr];
        float4 v  = *(const float4*)(g_agg1 + (size_t)gr * 64 + c4 * 4);
        float4 bb = *(const float4*)(b1 + c4 * 4);
        v.x = fmaxf(fmaf(v.x, dv, bb.x), 0.0f);
        v.y = fmaxf(fmaf(v.y, dv, bb.y), 0.0f);
        v.z = fmaxf(fmaf(v.z, dv, bb.z), 0.0f);
        v.w = fmaxf(fmaf(v.w, dv, bb.w), 0.0f);
        *(float4*)(&Ts[r][c4 * 4]) = v;
    }
    __syncthreads();
    const int r = tid >> 2;
    const int cg = tid & 3;
    float acc[8];
#pragma unroll
    for (int j = 0; j < 8; j++) acc[j] = 0.0f;
#pragma unroll
    for (int k = 0; k < 64; k++) {
        float a = Ts[r][k];
        float4 w0 = *(const float4*)(Ws + k * 32 + cg * 8);
        float4 w1 = *(const float4*)(Ws + k * 32 + cg * 8 + 4);
        acc[0] = fmaf(a, w0.x, acc[0]); acc[1] = fmaf(a, w0.y, acc[1]);
        acc[2] = fmaf(a, w0.z, acc[2]); acc[3] = fmaf(a, w0.w, acc[3]);
        acc[4] = fmaf(a, w1.x, acc[4]); acc[5] = fmaf(a, w1.y, acc[5]);
        acc[6] = fmaf(a, w1.z, acc[6]); acc[7] = fmaf(a, w1.w, acc[7]);
    }
    int gr = row0 + r;
    if (gr < NN) {
        float dv = g_dinv[gr];
        float4 o0 = make_float4(acc[0] * dv, acc[1] * dv, acc[2] * dv, acc[3] * dv);
        float4 o1 = make_float4(acc[4] * dv, acc[5] * dv, acc[6] * dv, acc[7] * dv);
        float* p = g_h2s + (size_t)gr * 32 + cg * 8;
        *(float4*)(p) = o0; *(float4*)(p + 4) = o1;
    }
}

__global__ void __launch_bounds__(256) k_gemm3(const float* __restrict__ W3,
                                               const float* __restrict__ b2) {
    __shared__ float Ts[64][36];
    __shared__ float Ws[32 * 16];
    const int tid = threadIdx.x;
    const int row0 = blockIdx.x * 64;
    if (tid < 128) *(float4*)(Ws + tid * 4) = *(const float4*)(W3 + tid * 4);
#pragma unroll
    for (int it = 0; it < 2; it++) {
        int i = it * 256 + tid;
        int r = i >> 3;
        int c4 = i & 7;
        int gr = row0 + r; if (gr >= NN) gr = NN - 1;
        float dv = g_dinv[gr];
        float4 v  = *(const float4*)(g_agg2 + (size_t)gr * 32 + c4 * 4);
        float4 bb = *(const float4*)(b2 + c4 * 4);
        v.x = fmaxf(fmaf(v.x, dv, bb.x), 0.0f);
        v.y = fmaxf(fmaf(v.y, dv, bb.y), 0.0f);
        v.z = fmaxf(fmaf(v.z, dv, bb.z), 0.0f);
        v.w = fmaxf(fmaf(v.w, dv, bb.w), 0.0f);
        *(float4*)(&Ts[r][c4 * 4]) = v;
    }
    __syncthreads();
    const int r = tid >> 2;
    const int cg = tid & 3;
    float acc[4] = {0.0f, 0.0f, 0.0f, 0.0f};
#pragma unroll
    for (int k = 0; k < 32; k++) {
        float a = Ts[r][k];
        float4 w = *(const float4*)(Ws + k * 16 + cg * 4);
        acc[0] = fmaf(a, w.x, acc[0]); acc[1] = fmaf(a, w.y, acc[1]);
        acc[2] = fmaf(a, w.z, acc[2]); acc[3] = fmaf(a, w.w, acc[3]);
    }
    int gr = row0 + r;
    if (gr < NN) {
        float dv = g_dinv[gr];
        float4 o = make_float4(acc[0] * dv, acc[1] * dv, acc[2] * dv, acc[3] * dv);
        *(float4*)(g_h3s + (size_t)gr * 16 + cg * 4) = o;
    }
}

extern "C" void kernel_launch(void* const* d_in, const int* in_sizes, int n_in,
                              void* d_out, int out_size) {
    const float* x  = (const float*)d_in[0];
    const int*   ei = (const int*)d_in[1];
    const float* W1 = (const float*)d_in[2];
    const float* b1 = (const float*)d_in[3];
    const float* W2 = (const float*)d_in[4];
    const float* b2 = (const float*)d_in[5];
    const float* W3 = (const float*)d_in[6];
    const float* b3 = (const float*)d_in[7];
    float* out = (float*)d_out;
    const int* src = ei;          // edge_index[0]
    const int* dst = ei + NE;     // edge_index[1]

    // CSR + dinv
    k_zero<<<(NN + 255) / 256, 256>>>();
    k_hist<<<(NE + 255) / 256, 256>>>(dst);
    k_scan1<<<NB_SCAN, 1024>>>();
    k_scan2<<<1, 128>>>();
    k_scan3<<<NB_SCAN, 1024>>>();
    k_fill<<<(NE + 255) / 256, 256>>>(src, dst);

    // layer 1
    k_gemm1<<<(NN + 127) / 128, 128>>>(x, W1);
    k_gather64<<<(NN * 32 + 255) / 256, 256>>>();
    // layer 2
    k_gemm2<<<(NN + 63) / 64, 256>>>(W2, b1);
    k_gather32<<<(NN * 32 + 255) / 256, 256>>>();
    // layer 3 + log_softmax
    k_gemm3<<<(NN + 63) / 64, 256>>>(W3, b2);
    k_gather16_final<<<(NN * 16 + 255) / 256, 256>>>(b3, out);
}

// round 5
// speedup vs baseline: 1.9112x; 1.0718x over previous
#include <cuda_runtime.h>
#include <cuda_fp16.h>

#define NN 100000
#define NE 1600000
#define NB_SCAN 98   // ceil(NN/1024)

// ---- scratch (__device__ globals; no allocations allowed) ----
__device__ __align__(16) float g_dinv[NN];
__device__ __align__(16) __half2 g_h1h[NN * 32];  // dinv-scaled layer-1 feats (fp16 msgs)
__device__ __align__(16) __half2 g_t1[NN * 32];   // relu(dinv*agg1+b1)  (gemm2 input)
__device__ __align__(16) __half2 g_h2h[NN * 16];
__device__ __align__(16) __half2 g_t2[NN * 16];
__device__ __align__(16) __half2 g_h3h[NN * 8];
__device__ int g_degi[NN];
__device__ int g_off[NN + 1];
__device__ int g_cur[NN];
__device__ int g_eidx[NE];
__device__ unsigned long long g_state[128];

// ================= CSR build + dinv =================
__global__ void k_hist(const int* __restrict__ dst) {
    int e = blockIdx.x * blockDim.x + threadIdx.x;
    if (e < NE) atomicAdd(&g_degi[dst[e]], 1);
}

// single-pass decoupled-lookback exclusive scan of g_degi -> g_off/g_cur, plus dinv
__global__ void __launch_bounds__(1024) k_scan() {
    __shared__ int wsum[32];
    __shared__ int s_prefix;
    const int tid = threadIdx.x, bid = blockIdx.x;
    const int i = bid * 1024 + tid;
    const int lane = tid & 31, w = tid >> 5;
    int deg = (i < NN) ? g_degi[i] : 0;
    int v = deg;
#pragma unroll
    for (int s = 1; s < 32; s <<= 1) {
        int t = __shfl_up_sync(~0u, v, s);
        if (lane >= s) v += t;
    }
    if (lane == 31) wsum[w] = v;
    __syncthreads();
    if (w == 0) {
        int x = wsum[lane];
#pragma unroll
        for (int s = 1; s < 32; s <<= 1) {
            int t = __shfl_up_sync(~0u, x, s);
            if (lane >= s) x += t;
        }
        wsum[lane] = x;  // inclusive scan of warp sums
    }
    __syncthreads();
    const int wpre = (w == 0) ? 0 : wsum[w - 1];
    const int excl = wpre + v - deg;
    const int total = wsum[31];

    if (w == 0) {
        if (lane == 0) {
            unsigned long long word =
                ((unsigned long long)(bid == 0 ? 2 : 1) << 32) | (unsigned)total;
            *(volatile unsigned long long*)&g_state[bid] = word;
        }
        if (bid > 0) {
            int run = 0;
            int base = bid - 1;
            while (true) {
                int p = base - lane;
                unsigned long long wd = (p >= 0)
                    ? *(volatile unsigned long long*)&g_state[p]
                    : (2ULL << 32);
                int st = (int)(wd >> 32);
                int val = (int)(wd & 0xffffffffu);
                if (__any_sync(~0u, st == 0)) continue;   // some pred not posted yet
                unsigned m2 = __ballot_sync(~0u, st == 2);
                if (m2) {
                    int L = __ffs(m2) - 1;
                    int c = (lane <= L) ? val : 0;
#pragma unroll
                    for (int s = 16; s >= 1; s >>= 1) c += __shfl_xor_sync(~0u, c, s);
                    run += c;
                    break;
                } else {
                    int c = (p >= 0) ? val : 0;
#pragma unroll
                    for (int s = 16; s >= 1; s >>= 1) c += __shfl_xor_sync(~0u, c, s);
                    run += c;
                    base -= 32;
                }
            }
            if (lane == 0) {
                *(volatile unsigned long long*)&g_state[bid] =
                    (2ULL << 32) | (unsigned)(total + run);
                s_prefix = run;
            }
        } else if (lane == 0) {
            s_prefix = 0;
        }
    }
    __syncthreads();
    const int off = excl + s_prefix;
    if (i < NN) {
        g_off[i] = off;
        g_cur[i] = off;
        g_dinv[i] = rsqrtf((float)(1 + deg));   // +1 = self-loop
    }
    if (i == 0) g_off[NN] = NE;
}

__global__ void k_fill(const int* __restrict__ src, const int* __restrict__ dst) {
    int e = blockIdx.x * blockDim.x + threadIdx.x;
    if (e < NE) {
        int p = atomicAdd(&g_cur[dst[e]], 1);
        g_eidx[p] = src[e];
    }
}

// ================= GEMM1 (TF32 MMA, cp.async 3-stage) =================
// h1h = fp16(dinv ⊙ (X @ W1)). Block 128x64, 128 threads, warp tile 32x64.
__global__ void __launch_bounds__(128) k_gemm1(const float* __restrict__ X,
                                               const float* __restrict__ W) {
    __shared__ unsigned As[3][128 * 20];
    __shared__ unsigned Bs[3][16 * 72];
    const int tid = threadIdx.x;
    const int lane = tid & 31;
    const int w = tid >> 5;
    const int row0 = blockIdx.x * 128;
    const int g = lane >> 2;
    const int tg = lane & 3;

    float c[2][8][4];
#pragma unroll
    for (int mt = 0; mt < 2; mt++)
#pragma unroll
        for (int nt = 0; nt < 8; nt++)
#pragma unroll
            for (int q = 0; q < 4; q++) c[mt][nt][q] = 0.0f;

#define ISSUE(kt, st)                                                            \
    {                                                                            \
        _Pragma("unroll") for (int it = 0; it < 4; it++) {                       \
            int i = it * 128 + tid;                                              \
            int r = i >> 2, kq = i & 3;                                          \
            int gr = row0 + r; if (gr >= NN) gr = NN - 1;                        \
            const float* gp = X + (size_t)gr * 512 + (kt) * 16 + kq * 4;         \
            unsigned sa = (unsigned)__cvta_generic_to_shared(&As[st][r * 20 + kq * 4]); \
            asm volatile("cp.async.cg.shared.global [%0], [%1], 16;" ::          \
                         "r"(sa), "l"(gp));                                      \
        }                                                                        \
        _Pragma("unroll") for (int it = 0; it < 2; it++) {                       \
            int i = it * 128 + tid;                                              \
            int k = i >> 4, n4 = i & 15;                                         \
            const float* gp = W + (size_t)((kt) * 16 + k) * 64 + n4 * 4;         \
            unsigned sa = (unsigned)__cvta_generic_to_shared(&Bs[st][k * 72 + n4 * 4]); \
            asm volatile("cp.async.cg.shared.global [%0], [%1], 16;" ::          \
                         "r"(sa), "l"(gp));                                      \
        }                                                                        \
        asm volatile("cp.async.commit_group;");                                  \
    }

    ISSUE(0, 0);
    ISSUE(1, 1);

    for (int kt = 0; kt < 32; kt++) {
        const int st = kt % 3;
        asm volatile("cp.async.wait_group 1;");
        __syncthreads();
        if (kt + 2 < 32) {
            const int st2 = (kt + 2) % 3;
            ISSUE(kt + 2, st2);
        } else {
            asm volatile("cp.async.commit_group;");
        }
#pragma unroll
        for (int kk = 0; kk < 16; kk += 8) {
            unsigned a[2][4];
#pragma unroll
            for (int mt = 0; mt < 2; mt++) {
                int r = w * 32 + mt * 16 + g;
                a[mt][0] = As[st][r * 20 + kk + tg];
                a[mt][1] = As[st][(r + 8) * 20 + kk + tg];
                a[mt][2] = As[st][r * 20 + kk + tg + 4];
                a[mt][3] = As[st][(r + 8) * 20 + kk + tg + 4];
            }
            unsigned b[8][2];
#pragma unroll
            for (int nt = 0; nt < 8; nt++) {
                int n = nt * 8 + g;
                b[nt][0] = Bs[st][(kk + tg) * 72 + n];
                b[nt][1] = Bs[st][(kk + tg + 4) * 72 + n];
            }
#pragma unroll
            for (int mt = 0; mt < 2; mt++)
#pragma unroll
                for (int nt = 0; nt < 8; nt++)
                    asm volatile(
                        "mma.sync.aligned.m16n8k8.row.col.f32.tf32.tf32.f32 "
                        "{%0,%1,%2,%3}, {%4,%5,%6,%7}, {%8,%9}, {%0,%1,%2,%3};"
                        : "+f"(c[mt][nt][0]), "+f"(c[mt][nt][1]),
                          "+f"(c[mt][nt][2]), "+f"(c[mt][nt][3])
                        : "r"(a[mt][0]), "r"(a[mt][1]), "r"(a[mt][2]), "r"(a[mt][3]),
                          "r"(b[nt][0]), "r"(b[nt][1]));
        }
    }
#undef ISSUE

    // epilogue: scale by dinv, store fp16 messages
#pragma unroll
    for (int mt = 0; mt < 2; mt++) {
        int r_base = row0 + w * 32 + mt * 16 + g;
#pragma unroll
        for (int half = 0; half < 2; half++) {
            int r = r_base + half * 8;
            if (r < NN) {
                float dv = g_dinv[r];
#pragma unroll
                for (int nt = 0; nt < 8; nt++) {
                    float ox = c[mt][nt][half * 2 + 0] * dv;
                    float oy = c[mt][nt][half * 2 + 1] * dv;
                    g_h1h[(size_t)r * 32 + nt * 4 + tg] = __floats2half2_rn(ox, oy);
                }
            }
        }
    }
}

// ================= CSR gathers (fp16 messages, fp32 accum) =================
// Layer 1: warp/node, lane holds feats {2l, 2l+1}; epilogue fuses relu(dv*a+b1).
__global__ void __launch_bounds__(256) k_gather64(const float* __restrict__ b1) {
    int n = (blockIdx.x * 256 + threadIdx.x) >> 5;
    int lane = threadIdx.x & 31;
    if (n >= NN) return;
    int j = g_off[n], e = g_off[n + 1];
    float2 a = __half22float2(g_h1h[(size_t)n * 32 + lane]);   // self-loop
    for (; j + 1 < e; j += 2) {
        int s0 = __ldg(&g_eidx[j]);
        int s1 = __ldg(&g_eidx[j + 1]);
        float2 u = __half22float2(__ldg(&g_h1h[(size_t)s0 * 32 + lane]));
        float2 q = __half22float2(__ldg(&g_h1h[(size_t)s1 * 32 + lane]));
        a.x += u.x + q.x;
        a.y += u.y + q.y;
    }
    if (j < e) {
        float2 u = __half22float2(__ldg(&g_h1h[(size_t)__ldg(&g_eidx[j]) * 32 + lane]));
        a.x += u.x; a.y += u.y;
    }
    float dv = g_dinv[n];
    float tx = fmaxf(fmaf(a.x, dv, __ldg(&b1[2 * lane])), 0.0f);
    float ty = fmaxf(fmaf(a.y, dv, __ldg(&b1[2 * lane + 1])), 0.0f);
    g_t1[(size_t)n * 32 + lane] = __floats2half2_rn(tx, ty);
}
// Layer 2: 16 lanes/node.
__global__ void __launch_bounds__(256) k_gather32(const float* __restrict__ b2) {
    int t = blockIdx.x * 256 + threadIdx.x;
    int n = t >> 4;
    int l = t & 15;
    if (n >= NN) return;
    int j = g_off[n], e = g_off[n + 1];
    float2 a = __half22float2(g_h2h[(size_t)n * 16 + l]);
    for (; j + 1 < e; j += 2) {
        int s0 = __ldg(&g_eidx[j]);
        int s1 = __ldg(&g_eidx[j + 1]);
        float2 u = __half22float2(__ldg(&g_h2h[(size_t)s0 * 16 + l]));
        float2 q = __half22float2(__ldg(&g_h2h[(size_t)s1 * 16 + l]));
        a.x += u.x + q.x;
        a.y += u.y + q.y;
    }
    if (j < e) {
        float2 u = __half22float2(__ldg(&g_h2h[(size_t)__ldg(&g_eidx[j]) * 16 + l]));
        a.x += u.x; a.y += u.y;
    }
    float dv = g_dinv[n];
    float tx = fmaxf(fmaf(a.x, dv, __ldg(&b2[2 * l])), 0.0f);
    float ty = fmaxf(fmaf(a.y, dv, __ldg(&b2[2 * l + 1])), 0.0f);
    g_t2[(size_t)n * 16 + l] = __floats2half2_rn(tx, ty);
}
// Layer 3 + bias + log_softmax fused: 8 lanes/node, 2 logits/lane.
__global__ void __launch_bounds__(256) k_gather16_final(const float* __restrict__ b3,
                                                        float* __restrict__ outv) {
    int t = blockIdx.x * 256 + threadIdx.x;
    int n = t >> 3;
    int l = t & 7;
    if (n >= NN) return;
    int j = g_off[n], e = g_off[n + 1];
    float2 a = __half22float2(g_h3h[(size_t)n * 8 + l]);
    for (; j + 1 < e; j += 2) {
        int s0 = __ldg(&g_eidx[j]);
        int s1 = __ldg(&g_eidx[j + 1]);
        float2 u = __half22float2(__ldg(&g_h3h[(size_t)s0 * 8 + l]));
        float2 q = __half22float2(__ldg(&g_h3h[(size_t)s1 * 8 + l]));
        a.x += u.x + q.x;
        a.y += u.y + q.y;
    }
    if (j < e) {
        float2 u = __half22float2(__ldg(&g_h3h[(size_t)__ldg(&g_eidx[j]) * 8 + l]));
        a.x += u.x; a.y += u.y;
    }
    float dv = g_dinv[n];
    float vx = fmaf(a.x, dv, __ldg(&b3[2 * l]));
    float vy = fmaf(a.y, dv, __ldg(&b3[2 * l + 1]));
    float m = fmaxf(vx, vy);
#pragma unroll
    for (int s = 4; s >= 1; s >>= 1) m = fmaxf(m, __shfl_xor_sync(0xffffffffu, m, s));
    float su = expf(vx - m) + expf(vy - m);
#pragma unroll
    for (int s = 4; s >= 1; s >>= 1) su += __shfl_xor_sync(0xffffffffu, su, s);
    float lse = m + logf(su);
    *(float2*)(outv + (size_t)n * 16 + 2 * l) = make_float2(vx - lse, vy - lse);
}

// ================= small GEMMs (inputs already transformed, fp16) =================
__global__ void __launch_bounds__(256) k_gemm2(const float* __restrict__ W2) {
    __shared__ float Ts[64][68];
    __shared__ float Ws[64 * 32];
    const int tid = threadIdx.x;
    const int row0 = blockIdx.x * 64;
#pragma unroll
    for (int it = 0; it < 2; it++) {
        int i = it * 256 + tid;
        *(float4*)(Ws + i * 4) = *(const float4*)(W2 + i * 4);
    }
#pragma unroll
    for (int it = 0; it < 8; it++) {
        int i = it * 256 + tid;
        int r = i >> 5;
        int cc = i & 31;
        int gr = row0 + r; if (gr >= NN) gr = NN - 1;
        float2 f = __half22float2(__ldg(&g_t1[(size_t)gr * 32 + cc]));
        Ts[r][2 * cc] = f.x;
        Ts[r][2 * cc + 1] = f.y;
    }
    __syncthreads();
    const int r = tid >> 2;
    const int cg = tid & 3;
    float acc[8];
#pragma unroll
    for (int j = 0; j < 8; j++) acc[j] = 0.0f;
#pragma unroll
    for (int k = 0; k < 64; k++) {
        float a = Ts[r][k];
        float4 w0 = *(const float4*)(Ws + k * 32 + cg * 8);
        float4 w1 = *(const float4*)(Ws + k * 32 + cg * 8 + 4);
        acc[0] = fmaf(a, w0.x, acc[0]); acc[1] = fmaf(a, w0.y, acc[1]);
        acc[2] = fmaf(a, w0.z, acc[2]); acc[3] = fmaf(a, w0.w, acc[3]);
        acc[4] = fmaf(a, w1.x, acc[4]); acc[5] = fmaf(a, w1.y, acc[5]);
        acc[6] = fmaf(a, w1.z, acc[6]); acc[7] = fmaf(a, w1.w, acc[7]);
    }
    int gr = row0 + r;
    if (gr < NN) {
        float dv = g_dinv[gr];
#pragma unroll
        for (int q = 0; q < 4; q++)
            g_h2h[(size_t)gr * 16 + cg * 4 + q] =
                __floats2half2_rn(acc[2 * q] * dv, acc[2 * q + 1] * dv);
    }
}

__global__ void __launch_bounds__(256) k_gemm3(const float* __restrict__ W3) {
    __shared__ float Ts[64][36];
    __shared__ float Ws[32 * 16];
    const int tid = threadIdx.x;
    const int row0 = blockIdx.x * 64;
    if (tid < 128) *(float4*)(Ws + tid * 4) = *(const float4*)(W3 + tid * 4);
#pragma unroll
    for (int it = 0; it < 4; it++) {
        int i = it * 256 + tid;
        int r = i >> 4;
        int cc = i & 15;
        int gr = row0 + r; if (gr >= NN) gr = NN - 1;
        float2 f = __half22float2(__ldg(&g_t2[(size_t)gr * 16 + cc]));
        Ts[r][2 * cc] = f.x;
        Ts[r][2 * cc + 1] = f.y;
    }
    __syncthreads();
    const int r = tid >> 2;
    const int cg = tid & 3;
    float acc[4] = {0.0f, 0.0f, 0.0f, 0.0f};
#pragma unroll
    for (int k = 0; k < 32; k++) {
        float a = Ts[r][k];
        float4 w = *(const float4*)(Ws + k * 16 + cg * 4);
        acc[0] = fmaf(a, w.x, acc[0]); acc[1] = fmaf(a, w.y, acc[1]);
        acc[2] = fmaf(a, w.z, acc[2]); acc[3] = fmaf(a, w.w, acc[3]);
    }
    int gr = row0 + r;
    if (gr < NN) {
        float dv = g_dinv[gr];
        g_h3h[(size_t)gr * 8 + cg * 2 + 0] = __floats2half2_rn(acc[0] * dv, acc[1] * dv);
        g_h3h[(size_t)gr * 8 + cg * 2 + 1] = __floats2half2_rn(acc[2] * dv, acc[3] * dv);
    }
}

extern "C" void kernel_launch(void* const* d_in, const int* in_sizes, int n_in,
                              void* d_out, int out_size) {
    const float* x  = (const float*)d_in[0];
    const int*   ei = (const int*)d_in[1];
    const float* W1 = (const float*)d_in[2];
    const float* b1 = (const float*)d_in[3];
    const float* W2 = (const float*)d_in[4];
    const float* b2 = (const float*)d_in[5];
    const float* W3 = (const float*)d_in[6];
    const float* b3 = (const float*)d_in[7];
    float* out = (float*)d_out;
    const int* src = ei;          // edge_index[0]
    const int* dst = ei + NE;     // edge_index[1]

    // zero degree histogram + lookback state (async memsets are graph-capturable)
    void* p_deg = nullptr; cudaGetSymbolAddress(&p_deg, g_degi);
    void* p_st  = nullptr; cudaGetSymbolAddress(&p_st, g_state);
    cudaMemsetAsync(p_deg, 0, NN * sizeof(int));
    cudaMemsetAsync(p_st, 0, 128 * sizeof(unsigned long long));

    // CSR + dinv
    k_hist<<<(NE + 255) / 256, 256>>>(dst);
    k_scan<<<NB_SCAN, 1024>>>();
    k_fill<<<(NE + 255) / 256, 256>>>(src, dst);

    // layer 1
    k_gemm1<<<(NN + 127) / 128, 128>>>(x, W1);
    k_gather64<<<(NN * 32) / 256, 256>>>(b1);
    // layer 2
    k_gemm2<<<(NN + 63) / 64, 256>>>(W2);
    k_gather32<<<(NN * 16) / 256, 256>>>(b2);
    // layer 3 + log_softmax
    k_gemm3<<<(NN + 63) / 64, 256>>>(W3);
    k_gather16_final<<<(NN * 8) / 256, 256>>>(b3, out);
}

// round 6
// speedup vs baseline: 1.9863x; 1.0393x over previous
#include <cuda_runtime.h>
#include <cuda_fp16.h>

#define NN 100000
#define NE 1600000
#define NB_SCAN 98   // ceil(NN/1024)

// ---- scratch (__device__ globals; no allocations allowed) ----
__device__ __align__(16) float g_dinv[NN];
__device__ __align__(16) __half2 g_h1h[NN * 32];  // UNSCALED layer-1 feats (fp16)
__device__ __align__(16) __half2 g_t1[NN * 32];   // relu(dinv*agg1+b1)  (gemm2 input)
__device__ __align__(16) __half2 g_h2h[NN * 16];  // dinv-scaled layer-2 feats
__device__ __align__(16) __half2 g_t2[NN * 16];
__device__ __align__(16) __half2 g_h3h[NN * 8];   // dinv-scaled layer-3 feats
__device__ int g_degi[NN];
__device__ int g_off[NN + 1];
__device__ int g_cur[NN];
__device__ int g_eidx[NE];
__device__ unsigned long long g_state[128];

// ================= CSR build + dinv =================
__global__ void k_hist(const int* __restrict__ dst) {
    int e = blockIdx.x * blockDim.x + threadIdx.x;
    if (e < NE) atomicAdd(&g_degi[dst[e]], 1);
}

// single-pass decoupled-lookback exclusive scan of g_degi -> g_off/g_cur, plus dinv
__global__ void __launch_bounds__(1024) k_scan() {
    __shared__ int wsum[32];
    __shared__ int s_prefix;
    const int tid = threadIdx.x, bid = blockIdx.x;
    const int i = bid * 1024 + tid;
    const int lane = tid & 31, w = tid >> 5;
    int deg = (i < NN) ? g_degi[i] : 0;
    int v = deg;
#pragma unroll
    for (int s = 1; s < 32; s <<= 1) {
        int t = __shfl_up_sync(~0u, v, s);
        if (lane >= s) v += t;
    }
    if (lane == 31) wsum[w] = v;
    __syncthreads();
    if (w == 0) {
        int x = wsum[lane];
#pragma unroll
        for (int s = 1; s < 32; s <<= 1) {
            int t = __shfl_up_sync(~0u, x, s);
            if (lane >= s) x += t;
        }
        wsum[lane] = x;  // inclusive scan of warp sums
    }
    __syncthreads();
    const int wpre = (w == 0) ? 0 : wsum[w - 1];
    const int excl = wpre + v - deg;
    const int total = wsum[31];

    if (w == 0) {
        if (lane == 0) {
            unsigned long long word =
                ((unsigned long long)(bid == 0 ? 2 : 1) << 32) | (unsigned)total;
            *(volatile unsigned long long*)&g_state[bid] = word;
        }
        if (bid > 0) {
            int run = 0;
            int base = bid - 1;
            while (true) {
                int p = base - lane;
                unsigned long long wd = (p >= 0)
                    ? *(volatile unsigned long long*)&g_state[p]
                    : (2ULL << 32);
                int st = (int)(wd >> 32);
                int val = (int)(wd & 0xffffffffu);
                if (__any_sync(~0u, st == 0)) continue;   // some pred not posted yet
                unsigned m2 = __ballot_sync(~0u, st == 2);
                if (m2) {
                    int L = __ffs(m2) - 1;
                    int c = (lane <= L) ? val : 0;
#pragma unroll
                    for (int s = 16; s >= 1; s >>= 1) c += __shfl_xor_sync(~0u, c, s);
                    run += c;
                    break;
                } else {
                    int c = (p >= 0) ? val : 0;
#pragma unroll
                    for (int s = 16; s >= 1; s >>= 1) c += __shfl_xor_sync(~0u, c, s);
                    run += c;
                    base -= 32;
                }
            }
            if (lane == 0) {
                *(volatile unsigned long long*)&g_state[bid] =
                    (2ULL << 32) | (unsigned)(total + run);
                s_prefix = run;
            }
        } else if (lane == 0) {
            s_prefix = 0;
        }
    }
    __syncthreads();
    const int off = excl + s_prefix;
    if (i < NN) {
        g_off[i] = off;
        g_cur[i] = off;
        g_dinv[i] = rsqrtf((float)(1 + deg));   // +1 = self-loop
    }
    if (i == 0) g_off[NN] = NE;
}

__global__ void k_fill(const int* __restrict__ src, const int* __restrict__ dst) {
    int e = blockIdx.x * blockDim.x + threadIdx.x;
    if (e < NE) {
        int p = atomicAdd(&g_cur[dst[e]], 1);
        g_eidx[p] = src[e];
    }
}

// ================= GEMM1 (TF32 MMA, cp.async 3-stage) =================
// h1h = fp16(X @ W1), UNSCALED — no dependency on CSR/dinv (enables overlap).
__global__ void __launch_bounds__(128) k_gemm1(const float* __restrict__ X,
                                               const float* __restrict__ W) {
    __shared__ unsigned As[3][128 * 20];
    __shared__ unsigned Bs[3][16 * 72];
    const int tid = threadIdx.x;
    const int lane = tid & 31;
    const int w = tid >> 5;
    const int row0 = blockIdx.x * 128;
    const int g = lane >> 2;
    const int tg = lane & 3;

    float c[2][8][4];
#pragma unroll
    for (int mt = 0; mt < 2; mt++)
#pragma unroll
        for (int nt = 0; nt < 8; nt++)
#pragma unroll
            for (int q = 0; q < 4; q++) c[mt][nt][q] = 0.0f;

#define ISSUE(kt, st)                                                            \
    {                                                                            \
        _Pragma("unroll") for (int it = 0; it < 4; it++) {                       \
            int i = it * 128 + tid;                                              \
            int r = i >> 2, kq = i & 3;                                          \
            int gr = row0 + r; if (gr >= NN) gr = NN - 1;                        \
            const float* gp = X + (size_t)gr * 512 + (kt) * 16 + kq * 4;         \
            unsigned sa = (unsigned)__cvta_generic_to_shared(&As[st][r * 20 + kq * 4]); \
            asm volatile("cp.async.cg.shared.global [%0], [%1], 16;" ::          \
                         "r"(sa), "l"(gp));                                      \
        }                                                                        \
        _Pragma("unroll") for (int it = 0; it < 2; it++) {                       \
            int i = it * 128 + tid;                                              \
            int k = i >> 4, n4 = i & 15;                                         \
            const float* gp = W + (size_t)((kt) * 16 + k) * 64 + n4 * 4;         \
            unsigned sa = (unsigned)__cvta_generic_to_shared(&Bs[st][k * 72 + n4 * 4]); \
            asm volatile("cp.async.cg.shared.global [%0], [%1], 16;" ::          \
                         "r"(sa), "l"(gp));                                      \
        }                                                                        \
        asm volatile("cp.async.commit_group;");                                  \
    }

    ISSUE(0, 0);
    ISSUE(1, 1);

    for (int kt = 0; kt < 32; kt++) {
        const int st = kt % 3;
        asm volatile("cp.async.wait_group 1;");
        __syncthreads();
        if (kt + 2 < 32) {
            const int st2 = (kt + 2) % 3;
            ISSUE(kt + 2, st2);
        } else {
            asm volatile("cp.async.commit_group;");
        }
#pragma unroll
        for (int kk = 0; kk < 16; kk += 8) {
            unsigned a[2][4];
#pragma unroll
            for (int mt = 0; mt < 2; mt++) {
                int r = w * 32 + mt * 16 + g;
                a[mt][0] = As[st][r * 20 + kk + tg];
                a[mt][1] = As[st][(r + 8) * 20 + kk + tg];
                a[mt][2] = As[st][r * 20 + kk + tg + 4];
                a[mt][3] = As[st][(r + 8) * 20 + kk + tg + 4];
            }
            unsigned b[8][2];
#pragma unroll
            for (int nt = 0; nt < 8; nt++) {
                int n = nt * 8 + g;
                b[nt][0] = Bs[st][(kk + tg) * 72 + n];
                b[nt][1] = Bs[st][(kk + tg + 4) * 72 + n];
            }
#pragma unroll
            for (int mt = 0; mt < 2; mt++)
#pragma unroll
                for (int nt = 0; nt < 8; nt++)
                    asm volatile(
                        "mma.sync.aligned.m16n8k8.row.col.f32.tf32.tf32.f32 "
                        "{%0,%1,%2,%3}, {%4,%5,%6,%7}, {%8,%9}, {%0,%1,%2,%3};"
                        : "+f"(c[mt][nt][0]), "+f"(c[mt][nt][1]),
                          "+f"(c[mt][nt][2]), "+f"(c[mt][nt][3])
                        : "r"(a[mt][0]), "r"(a[mt][1]), "r"(a[mt][2]), "r"(a[mt][3]),
                          "r"(b[nt][0]), "r"(b[nt][1]));
        }
    }
#undef ISSUE

    // epilogue: store UNSCALED fp16 features
#pragma unroll
    for (int mt = 0; mt < 2; mt++) {
        int r_base = row0 + w * 32 + mt * 16 + g;
#pragma unroll
        for (int half = 0; half < 2; half++) {
            int r = r_base + half * 8;
            if (r < NN) {
#pragma unroll
                for (int nt = 0; nt < 8; nt++) {
                    g_h1h[(size_t)r * 32 + nt * 4 + tg] =
                        __floats2half2_rn(c[mt][nt][half * 2 + 0],
                                          c[mt][nt][half * 2 + 1]);
                }
            }
        }
    }
}

// ================= CSR gathers (fp16 messages, fp32 accum) =================
// Layer 1: warp/node; per-edge scale by dinv[src] (broadcast load).
__global__ void __launch_bounds__(256) k_gather64(const float* __restrict__ b1) {
    int n = (blockIdx.x * 256 + threadIdx.x) >> 5;
    int lane = threadIdx.x & 31;
    if (n >= NN) return;
    int j = g_off[n], e = g_off[n + 1];
    float dvn = g_dinv[n];
    float2 h = __half22float2(g_h1h[(size_t)n * 32 + lane]);
    float2 a = make_float2(dvn * h.x, dvn * h.y);   // self-loop
    for (; j + 1 < e; j += 2) {
        int s0 = __ldg(&g_eidx[j]);
        int s1 = __ldg(&g_eidx[j + 1]);
        float d0 = __ldg(&g_dinv[s0]);
        float d1 = __ldg(&g_dinv[s1]);
        float2 u = __half22float2(__ldg(&g_h1h[(size_t)s0 * 32 + lane]));
        float2 q = __half22float2(__ldg(&g_h1h[(size_t)s1 * 32 + lane]));
        a.x = fmaf(d0, u.x, a.x); a.y = fmaf(d0, u.y, a.y);
        a.x = fmaf(d1, q.x, a.x); a.y = fmaf(d1, q.y, a.y);
    }
    if (j < e) {
        int s0 = __ldg(&g_eidx[j]);
        float d0 = __ldg(&g_dinv[s0]);
        float2 u = __half22float2(__ldg(&g_h1h[(size_t)s0 * 32 + lane]));
        a.x = fmaf(d0, u.x, a.x); a.y = fmaf(d0, u.y, a.y);
    }
    float tx = fmaxf(fmaf(a.x, dvn, __ldg(&b1[2 * lane])), 0.0f);
    float ty = fmaxf(fmaf(a.y, dvn, __ldg(&b1[2 * lane + 1])), 0.0f);
    g_t1[(size_t)n * 32 + lane] = __floats2half2_rn(tx, ty);
}
// Layer 2: 16 lanes/node (h2h already dinv-scaled by gemm2).
__global__ void __launch_bounds__(256) k_gather32(const float* __restrict__ b2) {
    int t = blockIdx.x * 256 + threadIdx.x;
    int n = t >> 4;
    int l = t & 15;
    if (n >= NN) return;
    int j = g_off[n], e = g_off[n + 1];
    float2 a = __half22float2(g_h2h[(size_t)n * 16 + l]);
    for (; j + 1 < e; j += 2) {
        int s0 = __ldg(&g_eidx[j]);
        int s1 = __ldg(&g_eidx[j + 1]);
        float2 u = __half22float2(__ldg(&g_h2h[(size_t)s0 * 16 + l]));
        float2 q = __half22float2(__ldg(&g_h2h[(size_t)s1 * 16 + l]));
        a.x += u.x + q.x;
        a.y += u.y + q.y;
    }
    if (j < e) {
        float2 u = __half22float2(__ldg(&g_h2h[(size_t)__ldg(&g_eidx[j]) * 16 + l]));
        a.x += u.x; a.y += u.y;
    }
    float dv = g_dinv[n];
    float tx = fmaxf(fmaf(a.x, dv, __ldg(&b2[2 * l])), 0.0f);
    float ty = fmaxf(fmaf(a.y, dv, __ldg(&b2[2 * l + 1])), 0.0f);
    g_t2[(size_t)n * 16 + l] = __floats2half2_rn(tx, ty);
}
// Layer 3 + bias + log_softmax fused: 8 lanes/node, 2 logits/lane.
__global__ void __launch_bounds__(256) k_gather16_final(const float* __restrict__ b3,
                                                        float* __restrict__ outv) {
    int t = blockIdx.x * 256 + threadIdx.x;
    int n = t >> 3;
    int l = t & 7;
    if (n >= NN) return;
    int j = g_off[n], e = g_off[n + 1];
    float2 a = __half22float2(g_h3h[(size_t)n * 8 + l]);
    for (; j + 1 < e; j += 2) {
        int s0 = __ldg(&g_eidx[j]);
        int s1 = __ldg(&g_eidx[j + 1]);
        float2 u = __half22float2(__ldg(&g_h3h[(size_t)s0 * 8 + l]));
        float2 q = __half22float2(__ldg(&g_h3h[(size_t)s1 * 8 + l]));
        a.x += u.x + q.x;
        a.y += u.y + q.y;
    }
    if (j < e) {
        float2 u = __half22float2(__ldg(&g_h3h[(size_t)__ldg(&g_eidx[j]) * 8 + l]));
        a.x += u.x; a.y += u.y;
    }
    float dv = g_dinv[n];
    float vx = fmaf(a.x, dv, __ldg(&b3[2 * l]));
    float vy = fmaf(a.y, dv, __ldg(&b3[2 * l + 1]));
    float m = fmaxf(vx, vy);
#pragma unroll
    for (int s = 4; s >= 1; s >>= 1) m = fmaxf(m, __shfl_xor_sync(0xffffffffu, m, s));
    float su = expf(vx - m) + expf(vy - m);
#pragma unroll
    for (int s = 4; s >= 1; s >>= 1) su += __shfl_xor_sync(0xffffffffu, su, s);
    float lse = m + logf(su);
    *(float2*)(outv + (size_t)n * 16 + 2 * l) = make_float2(vx - lse, vy - lse);
}

// ================= small GEMMs (inputs already transformed, fp16) =================
__global__ void __launch_bounds__(256) k_gemm2(const float* __restrict__ W2) {
    __shared__ float Ts[64][68];
    __shared__ float Ws[64 * 32];
    const int tid = threadIdx.x;
    const int row0 = blockIdx.x * 64;
#pragma unroll
    for (int it = 0; it < 2; it++) {
        int i = it * 256 + tid;
        *(float4*)(Ws + i * 4) = *(const float4*)(W2 + i * 4);
    }
#pragma unroll
    for (int it = 0; it < 8; it++) {
        int i = it * 256 + tid;
        int r = i >> 5;
        int cc = i & 31;
        int gr = row0 + r; if (gr >= NN) gr = NN - 1;
        float2 f = __half22float2(__ldg(&g_t1[(size_t)gr * 32 + cc]));
        Ts[r][2 * cc] = f.x;
        Ts[r][2 * cc + 1] = f.y;
    }
    __syncthreads();
    const int r = tid >> 2;
    const int cg = tid & 3;
    float acc[8];
#pragma unroll
    for (int j = 0; j < 8; j++) acc[j] = 0.0f;
#pragma unroll
    for (int k = 0; k < 64; k++) {
        float a = Ts[r][k];
        float4 w0 = *(const float4*)(Ws + k * 32 + cg * 8);
        float4 w1 = *(const float4*)(Ws + k * 32 + cg * 8 + 4);
        acc[0] = fmaf(a, w0.x, acc[0]); acc[1] = fmaf(a, w0.y, acc[1]);
        acc[2] = fmaf(a, w0.z, acc[2]); acc[3] = fmaf(a, w0.w, acc[3]);
        acc[4] = fmaf(a, w1.x, acc[4]); acc[5] = fmaf(a, w1.y, acc[5]);
        acc[6] = fmaf(a, w1.z, acc[6]); acc[7] = fmaf(a, w1.w, acc[7]);
    }
    int gr = row0 + r;
    if (gr < NN) {
        float dv = g_dinv[gr];
#pragma unroll
        for (int q = 0; q < 4; q++)
            g_h2h[(size_t)gr * 16 + cg * 4 + q] =
                __floats2half2_rn(acc[2 * q] * dv, acc[2 * q + 1] * dv);
    }
}

__global__ void __launch_bounds__(256) k_gemm3(const float* __restrict__ W3) {
    __shared__ float Ts[64][36];
    __shared__ float Ws[32 * 16];
    const int tid = threadIdx.x;
    const int row0 = blockIdx.x * 64;
    if (tid < 128) *(float4*)(Ws + tid * 4) = *(const float4*)(W3 + tid * 4);
#pragma unroll
    for (int it = 0; it < 4; it++) {
        int i = it * 256 + tid;
        int r = i >> 4;
        int cc = i & 15;
        int gr = row0 + r; if (gr >= NN) gr = NN - 1;
        float2 f = __half22float2(__ldg(&g_t2[(size_t)gr * 16 + cc]));
        Ts[r][2 * cc] = f.x;
        Ts[r][2 * cc + 1] = f.y;
    }
    __syncthreads();
    const int r = tid >> 2;
    const int cg = tid & 3;
    float acc[4] = {0.0f, 0.0f, 0.0f, 0.0f};
#pragma unroll
    for (int k = 0; k < 32; k++) {
        float a = Ts[r][k];
        float4 w = *(const float4*)(Ws + k * 16 + cg * 4);
        acc[0] = fmaf(a, w.x, acc[0]); acc[1] = fmaf(a, w.y, acc[1]);
        acc[2] = fmaf(a, w.z, acc[2]); acc[3] = fmaf(a, w.w, acc[3]);
    }
    int gr = row0 + r;
    if (gr < NN) {
        float dv = g_dinv[gr];
        g_h3h[(size_t)gr * 8 + cg * 2 + 0] = __floats2half2_rn(acc[0] * dv, acc[1] * dv);
        g_h3h[(size_t)gr * 8 + cg * 2 + 1] = __floats2half2_rn(acc[2] * dv, acc[3] * dv);
    }
}

extern "C" void kernel_launch(void* const* d_in, const int* in_sizes, int n_in,
                              void* d_out, int out_size) {
    const float* x  = (const float*)d_in[0];
    const int*   ei = (const int*)d_in[1];
    const float* W1 = (const float*)d_in[2];
    const float* b1 = (const float*)d_in[3];
    const float* W2 = (const float*)d_in[4];
    const float* b2 = (const float*)d_in[5];
    const float* W3 = (const float*)d_in[6];
    const float* b3 = (const float*)d_in[7];
    float* out = (float*)d_out;
    const int* src = ei;          // edge_index[0]
    const int* dst = ei + NE;     // edge_index[1]

    void* p_deg = nullptr; cudaGetSymbolAddress(&p_deg, g_degi);
    void* p_st  = nullptr; cudaGetSymbolAddress(&p_st, g_state);

    // Fork: CSR build on side stream, GEMM1 (independent) on main stream.
    // Host-side stream/event create+destroy happens only during capture,
    // never on graph replay; no device memory is allocated.
    cudaStream_t s2;
    cudaStreamCreateWithFlags(&s2, cudaStreamNonBlocking);
    cudaEvent_t e0, e1;
    cudaEventCreateWithFlags(&e0, cudaEventDisableTiming);
    cudaEventCreateWithFlags(&e1, cudaEventDisableTiming);

    cudaEventRecord(e0, 0);           // fork point on capture (legacy) stream
    cudaStreamWaitEvent(s2, e0, 0);

    // side stream: CSR + dinv
    cudaMemsetAsync(p_deg, 0, NN * sizeof(int), s2);
    cudaMemsetAsync(p_st, 0, 128 * sizeof(unsigned long long), s2);
    k_hist<<<(NE + 255) / 256, 256, 0, s2>>>(dst);
    k_scan<<<NB_SCAN, 1024, 0, s2>>>();
    k_fill<<<(NE + 255) / 256, 256, 0, s2>>>(src, dst);
    cudaEventRecord(e1, s2);

    // main stream: layer-1 GEMM (no CSR/dinv dependency)
    k_gemm1<<<(NN + 127) / 128, 128>>>(x, W1);

    cudaStreamWaitEvent(0, e1, 0);    // join

    // layer 1 aggregate
    k_gather64<<<(NN * 32) / 256, 256>>>(b1);
    // layer 2
    k_gemm2<<<(NN + 63) / 64, 256>>>(W2);
    k_gather32<<<(NN * 16) / 256, 256>>>(b2);
    // layer 3 + log_softmax
    k_gemm3<<<(NN + 63) / 64, 256>>>(W3);
    k_gather16_final<<<(NN * 8) / 256, 256>>>(b3, out);

    cudaStreamDestroy(s2);
    cudaEventDestroy(e0);
    cudaEventDestroy(e1);
}

// round 7
// speedup vs baseline: 2.1610x; 1.0880x over previous
#include <cuda_runtime.h>
#include <cuda_fp16.h>

#define NN 100000
#define NE 1600000
#define NB_SCAN 98   // ceil(NN/1024)

// ---- scratch (__device__ globals; no allocations allowed) ----
__device__ __align__(16) float g_dinv[NN];
__device__ __align__(16) __half2 g_h1h[NN * 32];  // UNSCALED layer-1 feats (fp16)
__device__ __align__(16) __half2 g_t1[NN * 32];   // relu(dinv*agg1+b1)  (gemm2 input)
__device__ __align__(16) __half2 g_h2h[NN * 16];  // dinv-scaled layer-2 feats
__device__ __align__(16) __half2 g_t2[NN * 16];
__device__ __align__(16) __half2 g_h3h[NN * 8];   // dinv-scaled layer-3 feats
__device__ int g_degi[NN];
__device__ int g_off[NN + 1];
__device__ int g_cur[NN];
__device__ int g_eidx[NE];
__device__ unsigned long long g_state[128];

__device__ __forceinline__ unsigned h2u(__half2 h) { return *(unsigned*)&h; }
__device__ __forceinline__ float2 u2f(unsigned u) { return __half22float2(*(__half2*)&u); }

// ================= CSR build + dinv =================
__global__ void k_hist(const int* __restrict__ dst) {
    int e = blockIdx.x * blockDim.x + threadIdx.x;
    if (e < NE) atomicAdd(&g_degi[dst[e]], 1);
}

// single-pass decoupled-lookback exclusive scan of g_degi -> g_off/g_cur, plus dinv
__global__ void __launch_bounds__(1024) k_scan() {
    __shared__ int wsum[32];
    __shared__ int s_prefix;
    const int tid = threadIdx.x, bid = blockIdx.x;
    const int i = bid * 1024 + tid;
    const int lane = tid & 31, w = tid >> 5;
    int deg = (i < NN) ? g_degi[i] : 0;
    int v = deg;
#pragma unroll
    for (int s = 1; s < 32; s <<= 1) {
        int t = __shfl_up_sync(~0u, v, s);
        if (lane >= s) v += t;
    }
    if (lane == 31) wsum[w] = v;
    __syncthreads();
    if (w == 0) {
        int x = wsum[lane];
#pragma unroll
        for (int s = 1; s < 32; s <<= 1) {
            int t = __shfl_up_sync(~0u, x, s);
            if (lane >= s) x += t;
        }
        wsum[lane] = x;
    }
    __syncthreads();
    const int wpre = (w == 0) ? 0 : wsum[w - 1];
    const int excl = wpre + v - deg;
    const int total = wsum[31];

    if (w == 0) {
        if (lane == 0) {
            unsigned long long word =
                ((unsigned long long)(bid == 0 ? 2 : 1) << 32) | (unsigned)total;
            *(volatile unsigned long long*)&g_state[bid] = word;
        }
        if (bid > 0) {
            int run = 0;
            int base = bid - 1;
            while (true) {
                int p = base - lane;
                unsigned long long wd = (p >= 0)
                    ? *(volatile unsigned long long*)&g_state[p]
                    : (2ULL << 32);
                int st = (int)(wd >> 32);
                int val = (int)(wd & 0xffffffffu);
                if (__any_sync(~0u, st == 0)) continue;
                unsigned m2 = __ballot_sync(~0u, st == 2);
                if (m2) {
                    int L = __ffs(m2) - 1;
                    int c = (lane <= L) ? val : 0;
#pragma unroll
                    for (int s = 16; s >= 1; s >>= 1) c += __shfl_xor_sync(~0u, c, s);
                    run += c;
                    break;
                } else {
                    int c = (p >= 0) ? val : 0;
#pragma unroll
                    for (int s = 16; s >= 1; s >>= 1) c += __shfl_xor_sync(~0u, c, s);
                    run += c;
                    base -= 32;
                }
            }
            if (lane == 0) {
                *(volatile unsigned long long*)&g_state[bid] =
                    (2ULL << 32) | (unsigned)(total + run);
                s_prefix = run;
            }
        } else if (lane == 0) {
            s_prefix = 0;
        }
    }
    __syncthreads();
    const int off = excl + s_prefix;
    if (i < NN) {
        g_off[i] = off;
        g_cur[i] = off;
        g_dinv[i] = rsqrtf((float)(1 + deg));
    }
    if (i == 0) g_off[NN] = NE;
}

__global__ void k_fill(const int* __restrict__ src, const int* __restrict__ dst) {
    int e = blockIdx.x * blockDim.x + threadIdx.x;
    if (e < NE) {
        int p = atomicAdd(&g_cur[dst[e]], 1);
        g_eidx[p] = src[e];
    }
}

// ================= GEMM1 (fp16 MMA m16n8k16 + ldmatrix) =================
// h1h = fp16(X @ W1), UNSCALED. Block 128x64, 128 threads, warp tile 32x64.
// fp16 mantissa == tf32 mantissa (10 bits) => same accuracy as tf32 path.
#define AS_S 24   // A smem stride in halves (word-stride 12: ldmatrix conflict-free)
#define BS_S 72   // B smem stride in halves (word-stride 36==4 mod 32: conflict-free)
__global__ void __launch_bounds__(128) k_gemm1(const float* __restrict__ X,
                                               const float* __restrict__ W) {
    __shared__ __align__(16) __half As[2][128 * AS_S];
    __shared__ __align__(16) __half Bs[2][16 * BS_S];
    const int tid = threadIdx.x;
    const int lane = tid & 31;
    const int w = tid >> 5;
    const int row0 = blockIdx.x * 128;
    const int g = lane >> 2;
    const int tg = lane & 3;

    float c[2][8][4];
#pragma unroll
    for (int mt = 0; mt < 2; mt++)
#pragma unroll
        for (int nt = 0; nt < 8; nt++)
#pragma unroll
            for (int q = 0; q < 4; q++) c[mt][nt][q] = 0.0f;

    float4 ra[4], rb[2];

#define LDG1(kt)                                                                  \
    {                                                                             \
        _Pragma("unroll") for (int it = 0; it < 4; it++) {                        \
            int i = it * 128 + tid;                                               \
            int r = i >> 2, kq = i & 3;                                           \
            int gr = row0 + r; if (gr >= NN) gr = NN - 1;                         \
            ra[it] = *(const float4*)(X + (size_t)gr * 512 + (kt) * 16 + kq * 4); \
        }                                                                         \
        _Pragma("unroll") for (int it = 0; it < 2; it++) {                        \
            int i = it * 128 + tid;                                               \
            int k = i >> 4, n4 = i & 15;                                          \
            rb[it] = *(const float4*)(W + (size_t)((kt) * 16 + k) * 64 + n4 * 4); \
        }                                                                         \
    }
#define STS1(buf)                                                                 \
    {                                                                             \
        _Pragma("unroll") for (int it = 0; it < 4; it++) {                        \
            int i = it * 128 + tid;                                               \
            int r = i >> 2, kq = i & 3;                                           \
            uint2 u = make_uint2(h2u(__floats2half2_rn(ra[it].x, ra[it].y)),      \
                                 h2u(__floats2half2_rn(ra[it].z, ra[it].w)));     \
            *(uint2*)(&As[buf][r * AS_S + kq * 4]) = u;                           \
        }                                                                         \
        _Pragma("unroll") for (int it = 0; it < 2; it++) {                        \
            int i = it * 128 + tid;                                               \
            int k = i >> 4, n4 = i & 15;                                          \
            uint2 u = make_uint2(h2u(__floats2half2_rn(rb[it].x, rb[it].y)),      \
                                 h2u(__floats2half2_rn(rb[it].z, rb[it].w)));     \
            *(uint2*)(&Bs[buf][k * BS_S + n4 * 4]) = u;                           \
        }                                                                         \
    }

    LDG1(0);
    STS1(0);
    __syncthreads();

    // ldmatrix lane-address components
    const int lm = lane >> 3;      // matrix id 0..3
    const int lr = lane & 7;       // row within matrix
    // A: matrices {rows 0-7 k0-7, rows 8-15 k0-7, rows 0-7 k8-15, rows 8-15 k8-15}
    const int a_row_off = (lm & 1) * 8 + lr;
    const int a_k_off = (lm >> 1) * 8;
    // B (.trans from [k][n]): {k0-7 n0-7, k8-15 n0-7, k0-7 n8-15, k8-15 n8-15}
    const int b_k = (lm & 1) * 8 + lr;
    const int b_n_off = (lm >> 1) * 8;

    for (int kt = 0; kt < 32; kt++) {
        const int buf = kt & 1;
        if (kt < 31) LDG1(kt + 1);

        unsigned a[2][4];
#pragma unroll
        for (int mt = 0; mt < 2; mt++) {
            unsigned sa = (unsigned)__cvta_generic_to_shared(
                &As[buf][(w * 32 + mt * 16 + a_row_off) * AS_S + a_k_off]);
            asm volatile("ldmatrix.sync.aligned.m8n8.x4.shared.b16 {%0,%1,%2,%3}, [%4];"
                         : "=r"(a[mt][0]), "=r"(a[mt][1]), "=r"(a[mt][2]), "=r"(a[mt][3])
                         : "r"(sa));
        }
#pragma unroll
        for (int nb = 0; nb < 4; nb++) {
            unsigned b0, b1, b2, b3;
            unsigned sb = (unsigned)__cvta_generic_to_shared(
                &Bs[buf][b_k * BS_S + nb * 16 + b_n_off]);
            asm volatile("ldmatrix.sync.aligned.m8n8.x4.trans.shared.b16 {%0,%1,%2,%3}, [%4];"
                         : "=r"(b0), "=r"(b1), "=r"(b2), "=r"(b3)
                         : "r"(sb));
#pragma unroll
            for (int mt = 0; mt < 2; mt++) {
                asm volatile(
                    "mma.sync.aligned.m16n8k16.row.col.f32.f16.f16.f32 "
                    "{%0,%1,%2,%3}, {%4,%5,%6,%7}, {%8,%9}, {%0,%1,%2,%3};"
                    : "+f"(c[mt][2 * nb][0]), "+f"(c[mt][2 * nb][1]),
                      "+f"(c[mt][2 * nb][2]), "+f"(c[mt][2 * nb][3])
                    : "r"(a[mt][0]), "r"(a[mt][1]), "r"(a[mt][2]), "r"(a[mt][3]),
                      "r"(b0), "r"(b1));
                asm volatile(
                    "mma.sync.aligned.m16n8k16.row.col.f32.f16.f16.f32 "
                    "{%0,%1,%2,%3}, {%4,%5,%6,%7}, {%8,%9}, {%0,%1,%2,%3};"
                    : "+f"(c[mt][2 * nb + 1][0]), "+f"(c[mt][2 * nb + 1][1]),
                      "+f"(c[mt][2 * nb + 1][2]), "+f"(c[mt][2 * nb + 1][3])
                    : "r"(a[mt][0]), "r"(a[mt][1]), "r"(a[mt][2]), "r"(a[mt][3]),
                      "r"(b2), "r"(b3));
            }
        }
        if (kt < 31) {
            __syncthreads();
            STS1(buf ^ 1);
            __syncthreads();
        }
    }
#undef LDG1
#undef STS1

    // epilogue: store UNSCALED fp16 features
#pragma unroll
    for (int mt = 0; mt < 2; mt++) {
        int r_base = row0 + w * 32 + mt * 16 + g;
#pragma unroll
        for (int half = 0; half < 2; half++) {
            int r = r_base + half * 8;
            if (r < NN) {
#pragma unroll
                for (int nt = 0; nt < 8; nt++) {
                    g_h1h[(size_t)r * 32 + nt * 4 + tg] =
                        __floats2half2_rn(c[mt][nt][half * 2 + 0],
                                          c[mt][nt][half * 2 + 1]);
                }
            }
        }
    }
}

// ================= CSR gathers (vectorized uint4, fp32 accum) =================
// Layer 1: 8 lanes/node, lane covers feats 8l..8l+7; per-edge dinv[src] scale.
__global__ void __launch_bounds__(256) k_gather64(const float* __restrict__ b1) {
    int t = blockIdx.x * 256 + threadIdx.x;
    int n = t >> 3;
    int l = t & 7;
    if (n >= NN) return;
    int j = g_off[n], e = g_off[n + 1];
    float dvn = g_dinv[n];
    const uint4* H = (const uint4*)g_h1h;
    uint4 hv = H[(size_t)n * 8 + l];
    float2 a0 = u2f(hv.x), a1 = u2f(hv.y), a2 = u2f(hv.z), a3 = u2f(hv.w);
    a0.x *= dvn; a0.y *= dvn; a1.x *= dvn; a1.y *= dvn;
    a2.x *= dvn; a2.y *= dvn; a3.x *= dvn; a3.y *= dvn;
#define ACC(u, d)                                                         \
    {                                                                     \
        float2 f0 = u2f((u).x), f1 = u2f((u).y), f2 = u2f((u).z), f3 = u2f((u).w); \
        a0.x = fmaf(d, f0.x, a0.x); a0.y = fmaf(d, f0.y, a0.y);           \
        a1.x = fmaf(d, f1.x, a1.x); a1.y = fmaf(d, f1.y, a1.y);           \
        a2.x = fmaf(d, f2.x, a2.x); a2.y = fmaf(d, f2.y, a2.y);           \
        a3.x = fmaf(d, f3.x, a3.x); a3.y = fmaf(d, f3.y, a3.y);           \
    }
    for (; j + 1 < e; j += 2) {
        int s0 = __ldg(&g_eidx[j]);
        int s1 = __ldg(&g_eidx[j + 1]);
        float d0 = __ldg(&g_dinv[s0]);
        float d1 = __ldg(&g_dinv[s1]);
        uint4 u = __ldg(&H[(size_t)s0 * 8 + l]);
        uint4 v = __ldg(&H[(size_t)s1 * 8 + l]);
        ACC(u, d0);
        ACC(v, d1);
    }
    if (j < e) {
        int s0 = __ldg(&g_eidx[j]);
        float d0 = __ldg(&g_dinv[s0]);
        uint4 u = __ldg(&H[(size_t)s0 * 8 + l]);
        ACC(u, d0);
    }
#undef ACC
    float4 bb0 = *(const float4*)(b1 + 8 * l);
    float4 bb1 = *(const float4*)(b1 + 8 * l + 4);
    uint4 o;
    o.x = h2u(__floats2half2_rn(fmaxf(fmaf(a0.x, dvn, bb0.x), 0.0f),
                                fmaxf(fmaf(a0.y, dvn, bb0.y), 0.0f)));
    o.y = h2u(__floats2half2_rn(fmaxf(fmaf(a1.x, dvn, bb0.z), 0.0f),
                                fmaxf(fmaf(a1.y, dvn, bb0.w), 0.0f)));
    o.z = h2u(__floats2half2_rn(fmaxf(fmaf(a2.x, dvn, bb1.x), 0.0f),
                                fmaxf(fmaf(a2.y, dvn, bb1.y), 0.0f)));
    o.w = h2u(__floats2half2_rn(fmaxf(fmaf(a3.x, dvn, bb1.z), 0.0f),
                                fmaxf(fmaf(a3.y, dvn, bb1.w), 0.0f)));
    ((uint4*)g_t1)[(size_t)n * 8 + l] = o;
}
// Layer 2: 4 lanes/node (h2h already dinv-scaled).
__global__ void __launch_bounds__(256) k_gather32(const float* __restrict__ b2) {
    int t = blockIdx.x * 256 + threadIdx.x;
    int n = t >> 2;
    int l = t & 3;
    if (n >= NN) return;
    int j = g_off[n], e = g_off[n + 1];
    const uint4* H = (const uint4*)g_h2h;
    uint4 hv = H[(size_t)n * 4 + l];
    float2 a0 = u2f(hv.x), a1 = u2f(hv.y), a2 = u2f(hv.z), a3 = u2f(hv.w);
#define ACC(u)                                                            \
    {                                                                     \
        float2 f0 = u2f((u).x), f1 = u2f((u).y), f2 = u2f((u).z), f3 = u2f((u).w); \
        a0.x += f0.x; a0.y += f0.y; a1.x += f1.x; a1.y += f1.y;           \
        a2.x += f2.x; a2.y += f2.y; a3.x += f3.x; a3.y += f3.y;           \
    }
    for (; j + 1 < e; j += 2) {
        int s0 = __ldg(&g_eidx[j]);
        int s1 = __ldg(&g_eidx[j + 1]);
        uint4 u = __ldg(&H[(size_t)s0 * 4 + l]);
        uint4 v = __ldg(&H[(size_t)s1 * 4 + l]);
        ACC(u);
        ACC(v);
    }
    if (j < e) {
        uint4 u = __ldg(&H[(size_t)__ldg(&g_eidx[j]) * 4 + l]);
        ACC(u);
    }
#undef ACC
    float dv = g_dinv[n];
    float4 bb0 = *(const float4*)(b2 + 8 * l);
    float4 bb1 = *(const float4*)(b2 + 8 * l + 4);
    uint4 o;
    o.x = h2u(__floats2half2_rn(fmaxf(fmaf(a0.x, dv, bb0.x), 0.0f),
                                fmaxf(fmaf(a0.y, dv, bb0.y), 0.0f)));
    o.y = h2u(__floats2half2_rn(fmaxf(fmaf(a1.x, dv, bb0.z), 0.0f),
                                fmaxf(fmaf(a1.y, dv, bb0.w), 0.0f)));
    o.z = h2u(__floats2half2_rn(fmaxf(fmaf(a2.x, dv, bb1.x), 0.0f),
                                fmaxf(fmaf(a2.y, dv, bb1.y), 0.0f)));
    o.w = h2u(__floats2half2_rn(fmaxf(fmaf(a3.x, dv, bb1.z), 0.0f),
                                fmaxf(fmaf(a3.y, dv, bb1.w), 0.0f)));
    ((uint4*)g_t2)[(size_t)n * 4 + l] = o;
}
// Layer 3 + bias + log_softmax fused: 2 lanes/node, 8 logits/lane.
__global__ void __launch_bounds__(256) k_gather16_final(const float* __restrict__ b3,
                                                        float* __restrict__ outv) {
    int t = blockIdx.x * 256 + threadIdx.x;
    int n = t >> 1;
    int l = t & 1;
    if (n >= NN) return;
    int j = g_off[n], e = g_off[n + 1];
    const uint4* H = (const uint4*)g_h3h;
    uint4 hv = H[(size_t)n * 2 + l];
    float2 a0 = u2f(hv.x), a1 = u2f(hv.y), a2 = u2f(hv.z), a3 = u2f(hv.w);
#define ACC(u)                                                            \
    {                                                                     \
        float2 f0 = u2f((u).x), f1 = u2f((u).y), f2 = u2f((u).z), f3 = u2f((u).w); \
        a0.x += f0.x; a0.y += f0.y; a1.x += f1.x; a1.y += f1.y;           \
        a2.x += f2.x; a2.y += f2.y; a3.x += f3.x; a3.y += f3.y;           \
    }
    for (; j + 1 < e; j += 2) {
        int s0 = __ldg(&g_eidx[j]);
        int s1 = __ldg(&g_eidx[j + 1]);
        uint4 u = __ldg(&H[(size_t)s0 * 2 + l]);
        uint4 v = __ldg(&H[(size_t)s1 * 2 + l]);
        ACC(u);
        ACC(v);
    }
    if (j < e) {
        uint4 u = __ldg(&H[(size_t)__ldg(&g_eidx[j]) * 2 + l]);
        ACC(u);
    }
#undef ACC
    float dv = g_dinv[n];
    float4 bb0 = *(const float4*)(b3 + 8 * l);
    float4 bb1 = *(const float4*)(b3 + 8 * l + 4);
    float v0 = fmaf(a0.x, dv, bb0.x), v1 = fmaf(a0.y, dv, bb0.y);
    float v2 = fmaf(a1.x, dv, bb0.z), v3 = fmaf(a1.y, dv, bb0.w);
    float v4 = fmaf(a2.x, dv, bb1.x), v5 = fmaf(a2.y, dv, bb1.y);
    float v6 = fmaf(a3.x, dv, bb1.z), v7 = fmaf(a3.y, dv, bb1.w);
    float m = fmaxf(fmaxf(fmaxf(v0, v1), fmaxf(v2, v3)),
                    fmaxf(fmaxf(v4, v5), fmaxf(v6, v7)));
    m = fmaxf(m, __shfl_xor_sync(0xffffffffu, m, 1));
    float su = expf(v0 - m) + expf(v1 - m) + expf(v2 - m) + expf(v3 - m)
             + expf(v4 - m) + expf(v5 - m) + expf(v6 - m) + expf(v7 - m);
    su += __shfl_xor_sync(0xffffffffu, su, 1);
    float lse = m + logf(su);
    float* po = outv + (size_t)n * 16 + 8 * l;
    *(float4*)(po) = make_float4(v0 - lse, v1 - lse, v2 - lse, v3 - lse);
    *(float4*)(po + 4) = make_float4(v4 - lse, v5 - lse, v6 - lse, v7 - lse);
}

// ================= small GEMMs (inputs already transformed, fp16) =================
__global__ void __launch_bounds__(256) k_gemm2(const float* __restrict__ W2) {
    __shared__ float Ts[64][68];
    __shared__ float Ws[64 * 32];
    const int tid = threadIdx.x;
    const int row0 = blockIdx.x * 64;
#pragma unroll
    for (int it = 0; it < 2; it++) {
        int i = it * 256 + tid;
        *(float4*)(Ws + i * 4) = *(const float4*)(W2 + i * 4);
    }
#pragma unroll
    for (int it = 0; it < 8; it++) {
        int i = it * 256 + tid;
        int r = i >> 5;
        int cc = i & 31;
        int gr = row0 + r; if (gr >= NN) gr = NN - 1;
        float2 f = __half22float2(__ldg(&g_t1[(size_t)gr * 32 + cc]));
        Ts[r][2 * cc] = f.x;
        Ts[r][2 * cc + 1] = f.y;
    }
    __syncthreads();
    const int r = tid >> 2;
    const int cg = tid & 3;
    float acc[8];
#pragma unroll
    for (int j = 0; j < 8; j++) acc[j] = 0.0f;
#pragma unroll
    for (int k = 0; k < 64; k++) {
        float a = Ts[r][k];
        float4 w0 = *(const float4*)(Ws + k * 32 + cg * 8);
        float4 w1 = *(const float4*)(Ws + k * 32 + cg * 8 + 4);
        acc[0] = fmaf(a, w0.x, acc[0]); acc[1] = fmaf(a, w0.y, acc[1]);
        acc[2] = fmaf(a, w0.z, acc[2]); acc[3] = fmaf(a, w0.w, acc[3]);
        acc[4] = fmaf(a, w1.x, acc[4]); acc[5] = fmaf(a, w1.y, acc[5]);
        acc[6] = fmaf(a, w1.z, acc[6]); acc[7] = fmaf(a, w1.w, acc[7]);
    }
    int gr = row0 + r;
    if (gr < NN) {
        float dv = g_dinv[gr];
#pragma unroll
        for (int q = 0; q < 4; q++)
            g_h2h[(size_t)gr * 16 + cg * 4 + q] =
                __floats2half2_rn(acc[2 * q] * dv, acc[2 * q + 1] * dv);
    }
}

__global__ void __launch_bounds__(256) k_gemm3(const float* __restrict__ W3) {
    __shared__ float Ts[64][36];
    __shared__ float Ws[32 * 16];
    const int tid = threadIdx.x;
    const int row0 = blockIdx.x * 64;
    if (tid < 128) *(float4*)(Ws + tid * 4) = *(const float4*)(W3 + tid * 4);
#pragma unroll
    for (int it = 0; it < 4; it++) {
        int i = it * 256 + tid;
        int r = i >> 4;
        int cc = i & 15;
        int gr = row0 + r; if (gr >= NN) gr = NN - 1;
        float2 f = __half22float2(__ldg(&g_t2[(size_t)gr * 16 + cc]));
        Ts[r][2 * cc] = f.x;
        Ts[r][2 * cc + 1] = f.y;
    }
    __syncthreads();
    const int r = tid >> 2;
    const int cg = tid & 3;
    float acc[4] = {0.0f, 0.0f, 0.0f, 0.0f};
#pragma unroll
    for (int k = 0; k < 32; k++) {
        float a = Ts[r][k];
        float4 w = *(const float4*)(Ws + k * 16 + cg * 4);
        acc[0] = fmaf(a, w.x, acc[0]); acc[1] = fmaf(a, w.y, acc[1]);
        acc[2] = fmaf(a, w.z, acc[2]); acc[3] = fmaf(a, w.w, acc[3]);
    }
    int gr = row0 + r;
    if (gr < NN) {
        float dv = g_dinv[gr];
        g_h3h[(size_t)gr * 8 + cg * 2 + 0] = __floats2half2_rn(acc[0] * dv, acc[1] * dv);
        g_h3h[(size_t)gr * 8 + cg * 2 + 1] = __floats2half2_rn(acc[2] * dv, acc[3] * dv);
    }
}

extern "C" void kernel_launch(void* const* d_in, const int* in_sizes, int n_in,
                              void* d_out, int out_size) {
    const float* x  = (const float*)d_in[0];
    const int*   ei = (const int*)d_in[1];
    const float* W1 = (const float*)d_in[2];
    const float* b1 = (const float*)d_in[3];
    const float* W2 = (const float*)d_in[4];
    const float* b2 = (const float*)d_in[5];
    const float* W3 = (const float*)d_in[6];
    const float* b3 = (const float*)d_in[7];
    float* out = (float*)d_out;
    const int* src = ei;
    const int* dst = ei + NE;

    void* p_deg = nullptr; cudaGetSymbolAddress(&p_deg, g_degi);
    void* p_st  = nullptr; cudaGetSymbolAddress(&p_st, g_state);

    cudaStream_t s2;
    cudaStreamCreateWithFlags(&s2, cudaStreamNonBlocking);
    cudaEvent_t e0, e1;
    cudaEventCreateWithFlags(&e0, cudaEventDisableTiming);
    cudaEventCreateWithFlags(&e1, cudaEventDisableTiming);

    cudaEventRecord(e0, 0);
    cudaStreamWaitEvent(s2, e0, 0);

    // side stream: CSR + dinv
    cudaMemsetAsync(p_deg, 0, NN * sizeof(int), s2);
    cudaMemsetAsync(p_st, 0, 128 * sizeof(unsigned long long), s2);
    k_hist<<<(NE + 255) / 256, 256, 0, s2>>>(dst);
    k_scan<<<NB_SCAN, 1024, 0, s2>>>();
    k_fill<<<(NE + 255) / 256, 256, 0, s2>>>(src, dst);
    cudaEventRecord(e1, s2);

    // main stream: layer-1 GEMM (independent of CSR/dinv)
    k_gemm1<<<(NN + 127) / 128, 128>>>(x, W1);

    cudaStreamWaitEvent(0, e1, 0);

    k_gather64<<<(NN * 8 + 255) / 256, 256>>>(b1);
    k_gemm2<<<(NN + 63) / 64, 256>>>(W2);
    k_gather32<<<(NN * 4 + 255) / 256, 256>>>(b2);
    k_gemm3<<<(NN + 63) / 64, 256>>>(W3);
    k_gather16_final<<<(NN * 2 + 255) / 256, 256>>>(b3, out);

    cudaStreamDestroy(s2);
    cudaEventDestroy(e0);
    cudaEventDestroy(e1);
}

// round 8
// speedup vs baseline: 2.1644x; 1.0016x over previous
#include <cuda_runtime.h>
#include <cuda_fp16.h>

#define NN 100000
#define NE 1600000
#define NB_SCAN 98   // ceil(NN/1024)
#define G1_STAGES 6
#define G1_AS 2560   // 128*20 words per stage
#define G1_BS 1152   // 16*72 words per stage
#define G1_SMEM ((G1_STAGES * (G1_AS + G1_BS)) * 4)   // 89088 bytes

// ---- scratch (__device__ globals; no allocations allowed) ----
__device__ __align__(16) float g_dinv[NN];
__device__ __align__(16) __half2 g_h1h[NN * 32];  // UNSCALED layer-1 feats (fp16)
__device__ __align__(16) __half2 g_t1[NN * 32];   // relu(dinv*agg1+b1)  (gemm2 input)
__device__ __align__(16) __half2 g_h2h[NN * 16];  // dinv-scaled layer-2 feats
__device__ __align__(16) __half2 g_t2[NN * 16];
__device__ __align__(16) __half2 g_h3h[NN * 8];   // dinv-scaled layer-3 feats
__device__ int g_degi[NN];
__device__ int g_off[NN + 1];
__device__ int g_cur[NN];
__device__ int g_eidx[NE];
__device__ unsigned long long g_state[128];

__device__ __forceinline__ unsigned h2u(__half2 h) { return *(unsigned*)&h; }
__device__ __forceinline__ float2 u2f(unsigned u) { return __half22float2(*(__half2*)&u); }

// ================= CSR build + dinv =================
__global__ void k_hist(const int* __restrict__ dst) {
    int e = blockIdx.x * blockDim.x + threadIdx.x;
    if (e < NE) atomicAdd(&g_degi[dst[e]], 1);
}

__global__ void __launch_bounds__(1024) k_scan() {
    __shared__ int wsum[32];
    __shared__ int s_prefix;
    const int tid = threadIdx.x, bid = blockIdx.x;
    const int i = bid * 1024 + tid;
    const int lane = tid & 31, w = tid >> 5;
    int deg = (i < NN) ? g_degi[i] : 0;
    int v = deg;
#pragma unroll
    for (int s = 1; s < 32; s <<= 1) {
        int t = __shfl_up_sync(~0u, v, s);
        if (lane >= s) v += t;
    }
    if (lane == 31) wsum[w] = v;
    __syncthreads();
    if (w == 0) {
        int x = wsum[lane];
#pragma unroll
        for (int s = 1; s < 32; s <<= 1) {
            int t = __shfl_up_sync(~0u, x, s);
            if (lane >= s) x += t;
        }
        wsum[lane] = x;
    }
    __syncthreads();
    const int wpre = (w == 0) ? 0 : wsum[w - 1];
    const int excl = wpre + v - deg;
    const int total = wsum[31];

    if (w == 0) {
        if (lane == 0) {
            unsigned long long word =
                ((unsigned long long)(bid == 0 ? 2 : 1) << 32) | (unsigned)total;
            *(volatile unsigned long long*)&g_state[bid] = word;
        }
        if (bid > 0) {
            int run = 0;
            int base = bid - 1;
            while (true) {
                int p = base - lane;
                unsigned long long wd = (p >= 0)
                    ? *(volatile unsigned long long*)&g_state[p]
                    : (2ULL << 32);
                int st = (int)(wd >> 32);
                int val = (int)(wd & 0xffffffffu);
                if (__any_sync(~0u, st == 0)) continue;
                unsigned m2 = __ballot_sync(~0u, st == 2);
                if (m2) {
                    int L = __ffs(m2) - 1;
                    int c = (lane <= L) ? val : 0;
#pragma unroll
                    for (int s = 16; s >= 1; s >>= 1) c += __shfl_xor_sync(~0u, c, s);
                    run += c;
                    break;
                } else {
                    int c = (p >= 0) ? val : 0;
#pragma unroll
                    for (int s = 16; s >= 1; s >>= 1) c += __shfl_xor_sync(~0u, c, s);
                    run += c;
                    base -= 32;
                }
            }
            if (lane == 0) {
                *(volatile unsigned long long*)&g_state[bid] =
                    (2ULL << 32) | (unsigned)(total + run);
                s_prefix = run;
            }
        } else if (lane == 0) {
            s_prefix = 0;
        }
    }
    __syncthreads();
    const int off = excl + s_prefix;
    if (i < NN) {
        g_off[i] = off;
        g_cur[i] = off;
        g_dinv[i] = rsqrtf((float)(1 + deg));
    }
    if (i == 0) g_off[NN] = NE;
}

__global__ void k_fill(const int* __restrict__ src, const int* __restrict__ dst) {
    int e = blockIdx.x * blockDim.x + threadIdx.x;
    if (e < NE) {
        int p = atomicAdd(&g_cur[dst[e]], 1);
        g_eidx[p] = src[e];
    }
}

// ================= GEMM1 (TF32 MMA, cp.async 6-stage deep pipeline) =================
// h1h = fp16(X @ W1), UNSCALED. Block 128x64, 128 threads, warp tile 32x64.
// Raw fp32 bits consumed as tf32 (truncation) — no cvt, no staging registers.
__global__ void __launch_bounds__(128) k_gemm1(const float* __restrict__ X,
                                               const float* __restrict__ W) {
    extern __shared__ unsigned smem_dyn[];
    unsigned* As = smem_dyn;                       // [6][128*20]
    unsigned* Bs = smem_dyn + G1_STAGES * G1_AS;   // [6][16*72]
    const int tid = threadIdx.x;
    const int lane = tid & 31;
    const int w = tid >> 5;
    const int row0 = blockIdx.x * 128;
    const int g = lane >> 2;
    const int tg = lane & 3;

    float c[2][8][4];
#pragma unroll
    for (int mt = 0; mt < 2; mt++)
#pragma unroll
        for (int nt = 0; nt < 8; nt++)
#pragma unroll
            for (int q = 0; q < 4; q++) c[mt][nt][q] = 0.0f;

#define ISSUE(kt, st)                                                            \
    {                                                                            \
        unsigned* Ab = As + (st) * G1_AS;                                        \
        unsigned* Bb = Bs + (st) * G1_BS;                                        \
        _Pragma("unroll") for (int it = 0; it < 4; it++) {                       \
            int i = it * 128 + tid;                                              \
            int r = i >> 2, kq = i & 3;                                          \
            int gr = row0 + r; if (gr >= NN) gr = NN - 1;                        \
            const float* gp = X + (size_t)gr * 512 + (kt) * 16 + kq * 4;         \
            unsigned sa = (unsigned)__cvta_generic_to_shared(&Ab[r * 20 + kq * 4]); \
            asm volatile("cp.async.cg.shared.global [%0], [%1], 16;" ::          \
                         "r"(sa), "l"(gp));                                      \
        }                                                                        \
        _Pragma("unroll") for (int it = 0; it < 2; it++) {                       \
            int i = it * 128 + tid;                                              \
            int k = i >> 4, n4 = i & 15;                                         \
            const float* gp = W + (size_t)((kt) * 16 + k) * 64 + n4 * 4;         \
            unsigned sa = (unsigned)__cvta_generic_to_shared(&Bb[k * 72 + n4 * 4]); \
            asm volatile("cp.async.cg.shared.global [%0], [%1], 16;" ::          \
                         "r"(sa), "l"(gp));                                      \
        }                                                                        \
        asm volatile("cp.async.commit_group;");                                  \
    }

    // prologue: fill 5 of 6 stages
#pragma unroll
    for (int p = 0; p < G1_STAGES - 1; p++) ISSUE(p, p);

    for (int kt = 0; kt < 32; kt++) {
        const int st = kt % G1_STAGES;
        asm volatile("cp.async.wait_group %0;" :: "n"(G1_STAGES - 2));
        __syncthreads();
        // issue tile kt+5 into stage (kt+5)%6 (that stage was consumed at iter kt-1)
        if (kt + G1_STAGES - 1 < 32) {
            ISSUE(kt + G1_STAGES - 1, (kt + G1_STAGES - 1) % G1_STAGES);
        } else {
            asm volatile("cp.async.commit_group;");
        }
        const unsigned* Ab = As + st * G1_AS;
        const unsigned* Bb = Bs + st * G1_BS;
#pragma unroll
        for (int kk = 0; kk < 16; kk += 8) {
            unsigned a[2][4];
#pragma unroll
            for (int mt = 0; mt < 2; mt++) {
                int r = w * 32 + mt * 16 + g;
                a[mt][0] = Ab[r * 20 + kk + tg];
                a[mt][1] = Ab[(r + 8) * 20 + kk + tg];
                a[mt][2] = Ab[r * 20 + kk + tg + 4];
                a[mt][3] = Ab[(r + 8) * 20 + kk + tg + 4];
            }
            unsigned b[8][2];
#pragma unroll
            for (int nt = 0; nt < 8; nt++) {
                int n = nt * 8 + g;
                b[nt][0] = Bb[(kk + tg) * 72 + n];
                b[nt][1] = Bb[(kk + tg + 4) * 72 + n];
            }
#pragma unroll
            for (int mt = 0; mt < 2; mt++)
#pragma unroll
                for (int nt = 0; nt < 8; nt++)
                    asm volatile(
                        "mma.sync.aligned.m16n8k8.row.col.f32.tf32.tf32.f32 "
                        "{%0,%1,%2,%3}, {%4,%5,%6,%7}, {%8,%9}, {%0,%1,%2,%3};"
                        : "+f"(c[mt][nt][0]), "+f"(c[mt][nt][1]),
                          "+f"(c[mt][nt][2]), "+f"(c[mt][nt][3])
                        : "r"(a[mt][0]), "r"(a[mt][1]), "r"(a[mt][2]), "r"(a[mt][3]),
                          "r"(b[nt][0]), "r"(b[nt][1]));
        }
        __syncthreads();   // stage st free for reissue next iter
    }
#undef ISSUE

    // epilogue: store UNSCALED fp16 features
#pragma unroll
    for (int mt = 0; mt < 2; mt++) {
        int r_base = row0 + w * 32 + mt * 16 + g;
#pragma unroll
        for (int half = 0; half < 2; half++) {
            int r = r_base + half * 8;
            if (r < NN) {
#pragma unroll
                for (int nt = 0; nt < 8; nt++) {
                    g_h1h[(size_t)r * 32 + nt * 4 + tg] =
                        __floats2half2_rn(c[mt][nt][half * 2 + 0],
                                          c[mt][nt][half * 2 + 1]);
                }
            }
        }
    }
}

// ================= CSR gathers (vectorized uint4, fp32 accum) =================
__global__ void __launch_bounds__(256) k_gather64(const float* __restrict__ b1) {
    int t = blockIdx.x * 256 + threadIdx.x;
    int n = t >> 3;
    int l = t & 7;
    if (n >= NN) return;
    int j = g_off[n], e = g_off[n + 1];
    float dvn = g_dinv[n];
    const uint4* H = (const uint4*)g_h1h;
    uint4 hv = H[(size_t)n * 8 + l];
    float2 a0 = u2f(hv.x), a1 = u2f(hv.y), a2 = u2f(hv.z), a3 = u2f(hv.w);
    a0.x *= dvn; a0.y *= dvn; a1.x *= dvn; a1.y *= dvn;
    a2.x *= dvn; a2.y *= dvn; a3.x *= dvn; a3.y *= dvn;
#define ACC(u, d)                                                         \
    {                                                                     \
        float2 f0 = u2f((u).x), f1 = u2f((u).y), f2 = u2f((u).z), f3 = u2f((u).w); \
        a0.x = fmaf(d, f0.x, a0.x); a0.y = fmaf(d, f0.y, a0.y);           \
        a1.x = fmaf(d, f1.x, a1.x); a1.y = fmaf(d, f1.y, a1.y);           \
        a2.x = fmaf(d, f2.x, a2.x); a2.y = fmaf(d, f2.y, a2.y);           \
        a3.x = fmaf(d, f3.x, a3.x); a3.y = fmaf(d, f3.y, a3.y);           \
    }
    for (; j + 1 < e; j += 2) {
        int s0 = __ldg(&g_eidx[j]);
        int s1 = __ldg(&g_eidx[j + 1]);
        float d0 = __ldg(&g_dinv[s0]);
        float d1 = __ldg(&g_dinv[s1]);
        uint4 u = __ldg(&H[(size_t)s0 * 8 + l]);
        uint4 v = __ldg(&H[(size_t)s1 * 8 + l]);
        ACC(u, d0);
        ACC(v, d1);
    }
    if (j < e) {
        int s0 = __ldg(&g_eidx[j]);
        float d0 = __ldg(&g_dinv[s0]);
        uint4 u = __ldg(&H[(size_t)s0 * 8 + l]);
        ACC(u, d0);
    }
#undef ACC
    float4 bb0 = *(const float4*)(b1 + 8 * l);
    float4 bb1 = *(const float4*)(b1 + 8 * l + 4);
    uint4 o;
    o.x = h2u(__floats2half2_rn(fmaxf(fmaf(a0.x, dvn, bb0.x), 0.0f),
                                fmaxf(fmaf(a0.y, dvn, bb0.y), 0.0f)));
    o.y = h2u(__floats2half2_rn(fmaxf(fmaf(a1.x, dvn, bb0.z), 0.0f),
                                fmaxf(fmaf(a1.y, dvn, bb0.w), 0.0f)));
    o.z = h2u(__floats2half2_rn(fmaxf(fmaf(a2.x, dvn, bb1.x), 0.0f),
                                fmaxf(fmaf(a2.y, dvn, bb1.y), 0.0f)));
    o.w = h2u(__floats2half2_rn(fmaxf(fmaf(a3.x, dvn, bb1.z), 0.0f),
                                fmaxf(fmaf(a3.y, dvn, bb1.w), 0.0f)));
    ((uint4*)g_t1)[(size_t)n * 8 + l] = o;
}
__global__ void __launch_bounds__(256) k_gather32(const float* __restrict__ b2) {
    int t = blockIdx.x * 256 + threadIdx.x;
    int n = t >> 2;
    int l = t & 3;
    if (n >= NN) return;
    int j = g_off[n], e = g_off[n + 1];
    const uint4* H = (const uint4*)g_h2h;
    uint4 hv = H[(size_t)n * 4 + l];
    float2 a0 = u2f(hv.x), a1 = u2f(hv.y), a2 = u2f(hv.z), a3 = u2f(hv.w);
#define ACC(u)                                                            \
    {                                                                     \
        float2 f0 = u2f((u).x), f1 = u2f((u).y), f2 = u2f((u).z), f3 = u2f((u).w); \
        a0.x += f0.x; a0.y += f0.y; a1.x += f1.x; a1.y += f1.y;           \
        a2.x += f2.x; a2.y += f2.y; a3.x += f3.x; a3.y += f3.y;           \
    }
    for (; j + 1 < e; j += 2) {
        int s0 = __ldg(&g_eidx[j]);
        int s1 = __ldg(&g_eidx[j + 1]);
        uint4 u = __ldg(&H[(size_t)s0 * 4 + l]);
        uint4 v = __ldg(&H[(size_t)s1 * 4 + l]);
        ACC(u);
        ACC(v);
    }
    if (j < e) {
        uint4 u = __ldg(&H[(size_t)__ldg(&g_eidx[j]) * 4 + l]);
        ACC(u);
    }
#undef ACC
    float dv = g_dinv[n];
    float4 bb0 = *(const float4*)(b2 + 8 * l);
    float4 bb1 = *(const float4*)(b2 + 8 * l + 4);
    uint4 o;
    o.x = h2u(__floats2half2_rn(fmaxf(fmaf(a0.x, dv, bb0.x), 0.0f),
                                fmaxf(fmaf(a0.y, dv, bb0.y), 0.0f)));
    o.y = h2u(__floats2half2_rn(fmaxf(fmaf(a1.x, dv, bb0.z), 0.0f),
                                fmaxf(fmaf(a1.y, dv, bb0.w), 0.0f)));
    o.z = h2u(__floats2half2_rn(fmaxf(fmaf(a2.x, dv, bb1.x), 0.0f),
                                fmaxf(fmaf(a2.y, dv, bb1.y), 0.0f)));
    o.w = h2u(__floats2half2_rn(fmaxf(fmaf(a3.x, dv, bb1.z), 0.0f),
                                fmaxf(fmaf(a3.y, dv, bb1.w), 0.0f)));
    ((uint4*)g_t2)[(size_t)n * 4 + l] = o;
}
__global__ void __launch_bounds__(256) k_gather16_final(const float* __restrict__ b3,
                                                        float* __restrict__ outv) {
    int t = blockIdx.x * 256 + threadIdx.x;
    int n = t >> 1;
    int l = t & 1;
    if (n >= NN) return;
    int j = g_off[n], e = g_off[n + 1];
    const uint4* H = (const uint4*)g_h3h;
    uint4 hv = H[(size_t)n * 2 + l];
    float2 a0 = u2f(hv.x), a1 = u2f(hv.y), a2 = u2f(hv.z), a3 = u2f(hv.w);
#define ACC(u)                                                            \
    {                                                                     \
        float2 f0 = u2f((u).x), f1 = u2f((u).y), f2 = u2f((u).z), f3 = u2f((u).w); \
        a0.x += f0.x; a0.y += f0.y; a1.x += f1.x; a1.y += f1.y;           \
        a2.x += f2.x; a2.y += f2.y; a3.x += f3.x; a3.y += f3.y;           \
    }
    for (; j + 1 < e; j += 2) {
        int s0 = __ldg(&g_eidx[j]);
        int s1 = __ldg(&g_eidx[j + 1]);
        uint4 u = __ldg(&H[(size_t)s0 * 2 + l]);
        uint4 v = __ldg(&H[(size_t)s1 * 2 + l]);
        ACC(u);
        ACC(v);
    }
    if (j < e) {
        uint4 u = __ldg(&H[(size_t)__ldg(&g_eidx[j]) * 2 + l]);
        ACC(u);
    }
#undef ACC
    float dv = g_dinv[n];
    float4 bb0 = *(const float4*)(b3 + 8 * l);
    float4 bb1 = *(const float4*)(b3 + 8 * l + 4);
    float v0 = fmaf(a0.x, dv, bb0.x), v1 = fmaf(a0.y, dv, bb0.y);
    float v2 = fmaf(a1.x, dv, bb0.z), v3 = fmaf(a1.y, dv, bb0.w);
    float v4 = fmaf(a2.x, dv, bb1.x), v5 = fmaf(a2.y, dv, bb1.y);
    float v6 = fmaf(a3.x, dv, bb1.z), v7 = fmaf(a3.y, dv, bb1.w);
    float m = fmaxf(fmaxf(fmaxf(v0, v1), fmaxf(v2, v3)),
                    fmaxf(fmaxf(v4, v5), fmaxf(v6, v7)));
    m = fmaxf(m, __shfl_xor_sync(0xffffffffu, m, 1));
    float su = expf(v0 - m) + expf(v1 - m) + expf(v2 - m) + expf(v3 - m)
             + expf(v4 - m) + expf(v5 - m) + expf(v6 - m) + expf(v7 - m);
    su += __shfl_xor_sync(0xffffffffu, su, 1);
    float lse = m + logf(su);
    float* po = outv + (size_t)n * 16 + 8 * l;
    *(float4*)(po) = make_float4(v0 - lse, v1 - lse, v2 - lse, v3 - lse);
    *(float4*)(po + 4) = make_float4(v4 - lse, v5 - lse, v6 - lse, v7 - lse);
}

// ================= small GEMMs (inputs already transformed, fp16) =================
__global__ void __launch_bounds__(256) k_gemm2(const float* __restrict__ W2) {
    __shared__ float Ts[64][68];
    __shared__ float Ws[64 * 32];
    const int tid = threadIdx.x;
    const int row0 = blockIdx.x * 64;
#pragma unroll
    for (int it = 0; it < 2; it++) {
        int i = it * 256 + tid;
        *(float4*)(Ws + i * 4) = *(const float4*)(W2 + i * 4);
    }
#pragma unroll
    for (int it = 0; it < 8; it++) {
        int i = it * 256 + tid;
        int r = i >> 5;
        int cc = i & 31;
        int gr = row0 + r; if (gr >= NN) gr = NN - 1;
        float2 f = __half22float2(__ldg(&g_t1[(size_t)gr * 32 + cc]));
        Ts[r][2 * cc] = f.x;
        Ts[r][2 * cc + 1] = f.y;
    }
    __syncthreads();
    const int r = tid >> 2;
    const int cg = tid & 3;
    float acc[8];
#pragma unroll
    for (int j = 0; j < 8; j++) acc[j] = 0.0f;
#pragma unroll
    for (int k = 0; k < 64; k++) {
        float a = Ts[r][k];
        float4 w0 = *(const float4*)(Ws + k * 32 + cg * 8);
        float4 w1 = *(const float4*)(Ws + k * 32 + cg * 8 + 4);
        acc[0] = fmaf(a, w0.x, acc[0]); acc[1] = fmaf(a, w0.y, acc[1]);
        acc[2] = fmaf(a, w0.z, acc[2]); acc[3] = fmaf(a, w0.w, acc[3]);
        acc[4] = fmaf(a, w1.x, acc[4]); acc[5] = fmaf(a, w1.y, acc[5]);
        acc[6] = fmaf(a, w1.z, acc[6]); acc[7] = fmaf(a, w1.w, acc[7]);
    }
    int gr = row0 + r;
    if (gr < NN) {
        float dv = g_dinv[gr];
#pragma unroll
        for (int q = 0; q < 4; q++)
            g_h2h[(size_t)gr * 16 + cg * 4 + q] =
                __floats2half2_rn(acc[2 * q] * dv, acc[2 * q + 1] * dv);
    }
}

__global__ void __launch_bounds__(256) k_gemm3(const float* __restrict__ W3) {
    __shared__ float Ts[64][36];
    __shared__ float Ws[32 * 16];
    const int tid = threadIdx.x;
    const int row0 = blockIdx.x * 64;
    if (tid < 128) *(float4*)(Ws + tid * 4) = *(const float4*)(W3 + tid * 4);
#pragma unroll
    for (int it = 0; it < 4; it++) {
        int i = it * 256 + tid;
        int r = i >> 4;
        int cc = i & 15;
        int gr = row0 + r; if (gr >= NN) gr = NN - 1;
        float2 f = __half22float2(__ldg(&g_t2[(size_t)gr * 16 + cc]));
        Ts[r][2 * cc] = f.x;
        Ts[r][2 * cc + 1] = f.y;
    }
    __syncthreads();
    const int r = tid >> 2;
    const int cg = tid & 3;
    float acc[4] = {0.0f, 0.0f, 0.0f, 0.0f};
#pragma unroll
    for (int k = 0; k < 32; k++) {
        float a = Ts[r][k];
        float4 w = *(const float4*)(Ws + k * 16 + cg * 4);
        acc[0] = fmaf(a, w.x, acc[0]); acc[1] = fmaf(a, w.y, acc[1]);
        acc[2] = fmaf(a, w.z, acc[2]); acc[3] = fmaf(a, w.w, acc[3]);
    }
    int gr = row0 + r;
    if (gr < NN) {
        float dv = g_dinv[gr];
        g_h3h[(size_t)gr * 8 + cg * 2 + 0] = __floats2half2_rn(acc[0] * dv, acc[1] * dv);
        g_h3h[(size_t)gr * 8 + cg * 2 + 1] = __floats2half2_rn(acc[2] * dv, acc[3] * dv);
    }
}

extern "C" void kernel_launch(void* const* d_in, const int* in_sizes, int n_in,
                              void* d_out, int out_size) {
    const float* x  = (const float*)d_in[0];
    const int*   ei = (const int*)d_in[1];
    const float* W1 = (const float*)d_in[2];
    const float* b1 = (const float*)d_in[3];
    const float* W2 = (const float*)d_in[4];
    const float* b2 = (const float*)d_in[5];
    const float* W3 = (const float*)d_in[6];
    const float* b3 = (const float*)d_in[7];
    float* out = (float*)d_out;
    const int* src = ei;
    const int* dst = ei + NE;

    void* p_deg = nullptr; cudaGetSymbolAddress(&p_deg, g_degi);
    void* p_st  = nullptr; cudaGetSymbolAddress(&p_st, g_state);

    cudaFuncSetAttribute(k_gemm1, cudaFuncAttributeMaxDynamicSharedMemorySize, G1_SMEM);

    cudaStream_t s2;
    cudaStreamCreateWithFlags(&s2, cudaStreamNonBlocking);
    cudaEvent_t e0, e1;
    cudaEventCreateWithFlags(&e0, cudaEventDisableTiming);
    cudaEventCreateWithFlags(&e1, cudaEventDisableTiming);

    cudaEventRecord(e0, 0);
    cudaStreamWaitEvent(s2, e0, 0);

    // side stream: CSR + dinv
    cudaMemsetAsync(p_deg, 0, NN * sizeof(int), s2);
    cudaMemsetAsync(p_st, 0, 128 * sizeof(unsigned long long), s2);
    k_hist<<<(NE + 255) / 256, 256, 0, s2>>>(dst);
    k_scan<<<NB_SCAN, 1024, 0, s2>>>();
    k_fill<<<(NE + 255) / 256, 256, 0, s2>>>(src, dst);
    cudaEventRecord(e1, s2);

    // main stream: layer-1 GEMM (independent of CSR/dinv)
    k_gemm1<<<(NN + 127) / 128, 128, G1_SMEM>>>(x, W1);

    cudaStreamWaitEvent(0, e1, 0);

    k_gather64<<<(NN * 8 + 255) / 256, 256>>>(b1);
    k_gemm2<<<(NN + 63) / 64, 256>>>(W2);
    k_gather32<<<(NN * 4 + 255) / 256, 256>>>(b2);
    k_gemm3<<<(NN + 63) / 64, 256>>>(W3);
    k_gather16_final<<<(NN * 2 + 255) / 256, 256>>>(b3, out);

    cudaStreamDestroy(s2);
    cudaEventDestroy(e0);
    cudaEventDestroy(e1);
}